// round 3
// baseline (speedup 1.0000x reference)
#include <cuda_runtime.h>
#include <cuda_bf16.h>
#include <cstddef>

// ---------------------------------------------------------------------------
// FeaturePropogate: 2x (KNN top-8 inverse-distance interp) + 4x (GEMM+BN+ReLU)
// All activations kept point-major [n][c]; GEMMs are NT form.
// fp32 math with packed fma.rn.f32x2 (FFMA2) in the GEMM inner loop.
// ---------------------------------------------------------------------------

#define B_     4
#define N0_    8192
#define N1_    2048
#define N2_    512

// scratch (device globals: no allocation allowed)
__device__ float g_X1[(size_t)B_ * N1_ * 320];   // concat(l1_feat, interp2) pm
__device__ float g_Y1[(size_t)B_ * N1_ * 640];
__device__ float g_F [(size_t)B_ * N1_ * 640];   // mlp_2_1 output pm
__device__ float g_X3[(size_t)B_ * N0_ * 704];   // concat(radar, interp1) pm
__device__ float g_Y3[(size_t)B_ * N0_ * 640];

typedef unsigned long long u64;

__device__ __forceinline__ u64 fma2(u64 a, u64 b, u64 c) {
    u64 d;
    asm("fma.rn.f32x2 %0, %1, %2, %3;" : "=l"(d) : "l"(a), "l"(b), "l"(c));
    return d;
}
__device__ __forceinline__ void unpack2(u64 v, float& lo, float& hi) {
    asm("mov.b64 {%0, %1}, %2;" : "=f"(lo), "=f"(hi) : "l"(v));
}

// ---------------------------------------------------------------------------
// KNN level2 -> level1 + build X1 = [l1_feat(128) | interp(192)] point-major
// One block = 256 points. Phase 1: per-thread top-8 (coalesced column reads).
// Phase 2: warp-per-point gather (coalesced 192-float rows, L2 resident).
// ---------------------------------------------------------------------------
__global__ __launch_bounds__(256)
void knn_build_x1(const float* __restrict__ l1_to_l2,  // [B,512,2048]
                  const float* __restrict__ l1_feat,   // [B,2048,128]
                  const float* __restrict__ l2_feat,   // [B,512,192]
                  float* __restrict__ X1)              // [B,2048,320]
{
    __shared__ int   sh_i[256][8];
    __shared__ float sh_w[256][8];
    const int b    = blockIdx.y;
    const int base = blockIdx.x * 256;
    const int tid  = threadIdx.x;
    {
        float bd[8]; int bi[8];
        #pragma unroll
        for (int j = 0; j < 8; ++j) { bd[j] = 3.4e38f; bi[j] = 0; }
        const float* col = l1_to_l2 + (size_t)b * N2_ * N1_ + base + tid;
        #pragma unroll 4
        for (int m = 0; m < N2_; ++m) {
            float v = __ldg(col + (size_t)m * N1_);
            if (v < bd[7]) {
                bd[7] = v; bi[7] = m;
                #pragma unroll
                for (int q = 7; q >= 1; --q) {
                    if (bd[q] < bd[q-1]) {
                        float td = bd[q]; bd[q] = bd[q-1]; bd[q-1] = td;
                        int   ti = bi[q]; bi[q] = bi[q-1]; bi[q-1] = ti;
                    }
                }
            }
        }
        float w[8], s = 0.f;
        #pragma unroll
        for (int j = 0; j < 8; ++j) { w[j] = 1.f / (bd[j] + 1e-8f); s += w[j]; }
        float inv = 1.f / (s + 1e-8f);
        #pragma unroll
        for (int j = 0; j < 8; ++j) { sh_i[tid][j] = bi[j]; sh_w[tid][j] = w[j] * inv; }
    }
    __syncthreads();
    const int warp = tid >> 5, lane = tid & 31;
    for (int pp = 0; pp < 32; ++pp) {
        const int p  = warp * 32 + pp;
        const int n1 = base + p;
        float* xrow = X1 + ((size_t)b * N1_ + n1) * 320;
        // copy l1_feat (128 floats, one float4 per lane)
        float4 lv = *(const float4*)(l1_feat + ((size_t)b * N1_ + n1) * 128 + lane * 4);
        *(float4*)(xrow + lane * 4) = lv;
        // interp 192 channels
        float acc[6];
        #pragma unroll
        for (int r = 0; r < 6; ++r) acc[r] = 0.f;
        #pragma unroll
        for (int j = 0; j < 8; ++j) {
            const int   idx = sh_i[p][j];
            const float wj  = sh_w[p][j];
            const float* f  = l2_feat + ((size_t)b * N2_ + idx) * 192;
            #pragma unroll
            for (int r = 0; r < 6; ++r) acc[r] += wj * __ldg(f + lane + 32 * r);
        }
        #pragma unroll
        for (int r = 0; r < 6; ++r) xrow[128 + lane + 32 * r] = acc[r];
    }
}

// ---------------------------------------------------------------------------
// KNN level1 -> level0 + build X3 = [radar(64) | interp(640)] point-major
// ---------------------------------------------------------------------------
__global__ __launch_bounds__(256)
void knn_build_x3(const float* __restrict__ l0_to_l1,  // [B,2048,8192]
                  const float* __restrict__ radar,     // [B,8192,64]
                  const float* __restrict__ Fpm,       // [B,2048,640]
                  float* __restrict__ X3)              // [B,8192,704]
{
    __shared__ int   sh_i[256][8];
    __shared__ float sh_w[256][8];
    const int b    = blockIdx.y;
    const int base = blockIdx.x * 256;
    const int tid  = threadIdx.x;
    {
        float bd[8]; int bi[8];
        #pragma unroll
        for (int j = 0; j < 8; ++j) { bd[j] = 3.4e38f; bi[j] = 0; }
        const float* col = l0_to_l1 + (size_t)b * N1_ * N0_ + base + tid;
        #pragma unroll 4
        for (int m = 0; m < N1_; ++m) {
            float v = __ldg(col + (size_t)m * N0_);
            if (v < bd[7]) {
                bd[7] = v; bi[7] = m;
                #pragma unroll
                for (int q = 7; q >= 1; --q) {
                    if (bd[q] < bd[q-1]) {
                        float td = bd[q]; bd[q] = bd[q-1]; bd[q-1] = td;
                        int   ti = bi[q]; bi[q] = bi[q-1]; bi[q-1] = ti;
                    }
                }
            }
        }
        float w[8], s = 0.f;
        #pragma unroll
        for (int j = 0; j < 8; ++j) { w[j] = 1.f / (bd[j] + 1e-8f); s += w[j]; }
        float inv = 1.f / (s + 1e-8f);
        #pragma unroll
        for (int j = 0; j < 8; ++j) { sh_i[tid][j] = bi[j]; sh_w[tid][j] = w[j] * inv; }
    }
    __syncthreads();
    const int warp = tid >> 5, lane = tid & 31;
    for (int pp = 0; pp < 32; ++pp) {
        const int p  = warp * 32 + pp;
        const int n0 = base + p;
        float* xrow = X3 + ((size_t)b * N0_ + n0) * 704;
        // radar copy (64 floats, float2 per lane)
        float2 rv = *(const float2*)(radar + ((size_t)b * N0_ + n0) * 64 + lane * 2);
        *(float2*)(xrow + lane * 2) = rv;
        // interp 640 channels
        float acc[20];
        #pragma unroll
        for (int r = 0; r < 20; ++r) acc[r] = 0.f;
        #pragma unroll
        for (int j = 0; j < 8; ++j) {
            const int   idx = sh_i[p][j];
            const float wj  = sh_w[p][j];
            const float* f  = Fpm + ((size_t)b * N1_ + idx) * 640;
            #pragma unroll
            for (int r = 0; r < 20; ++r) acc[r] += wj * __ldg(f + lane + 32 * r);
        }
        #pragma unroll
        for (int r = 0; r < 20; ++r) xrow[64 + lane + 32 * r] = acc[r];
    }
}

// ---------------------------------------------------------------------------
// Fused GEMM + BN(eval) + ReLU.  NT form: Y[o][n] = sum_k W[o][k] * X[n][k]
// 128(O) x 128(N) x 16(K) tiles, 256 threads, 8x8 microtile, fma.rn.f32x2.
// W is stored in shared duplicated ((w,w) pairs) so one LDS.128 feeds 2 o's.
// pm_out=1 -> Y[n][o] (point-major), pm_out=0 -> Y[o][n] (channel-major).
// All dims are multiples of the tile sizes for this problem (no bounds checks).
// ---------------------------------------------------------------------------
__global__ __launch_bounds__(256, 2)
void gemm_bn_relu(const float* __restrict__ W,     // [O,K]
                  const float* __restrict__ X,     // [B][N][K]
                  float* __restrict__ Y,
                  const float* __restrict__ bias,
                  const float* __restrict__ gamma,
                  const float* __restrict__ beta,
                  int K, int N, int O, int pm_out)
{
    __shared__ float Wsd[16][256];   // duplicated pairs: Wsd[k][2*o..2*o+1]
    __shared__ float Xs [16][128];

    const int b  = blockIdx.z;
    const float* Xb = X + (size_t)b * N * K;
    float*       Yb = Y + (size_t)b * N * O;
    const int o0 = blockIdx.y * 128;
    const int n0 = blockIdx.x * 128;
    const int t  = threadIdx.x;
    const int tx = t & 15;
    const int ty = t >> 4;

    u64 acc[8][4];
    #pragma unroll
    for (int i = 0; i < 8; ++i)
        #pragma unroll
        for (int j = 0; j < 4; ++j) acc[i][j] = 0ull;

    for (int k0 = 0; k0 < K; k0 += 16) {
        // load W tile (128 o x 16 k), duplicate into pairs
        #pragma unroll
        for (int r = 0; r < 2; ++r) {
            int idx = t + r * 256;
            int o = idx >> 2, kc = idx & 3;
            float4 wv = *(const float4*)(W + (size_t)(o0 + o) * K + k0 + kc * 4);
            float2 p;
            p.x = wv.x; p.y = wv.x; *(float2*)&Wsd[kc*4+0][2*o] = p;
            p.x = wv.y; p.y = wv.y; *(float2*)&Wsd[kc*4+1][2*o] = p;
            p.x = wv.z; p.y = wv.z; *(float2*)&Wsd[kc*4+2][2*o] = p;
            p.x = wv.w; p.y = wv.w; *(float2*)&Wsd[kc*4+3][2*o] = p;
        }
        // load X tile (128 n x 16 k)
        #pragma unroll
        for (int r = 0; r < 2; ++r) {
            int idx = t + r * 256;
            int n = idx >> 2, kc = idx & 3;
            float4 xv = *(const float4*)(Xb + (size_t)(n0 + n) * K + k0 + kc * 4);
            Xs[kc*4+0][n] = xv.x;
            Xs[kc*4+1][n] = xv.y;
            Xs[kc*4+2][n] = xv.z;
            Xs[kc*4+3][n] = xv.w;
        }
        __syncthreads();
        #pragma unroll
        for (int kk = 0; kk < 16; ++kk) {
            ulonglong2 xa = *(const ulonglong2*)&Xs[kk][tx * 4];
            ulonglong2 xb = *(const ulonglong2*)&Xs[kk][64 + tx * 4];
            ulonglong2 w0 = *(const ulonglong2*)&Wsd[kk][ty * 8];
            ulonglong2 w1 = *(const ulonglong2*)&Wsd[kk][ty * 8 + 4];
            ulonglong2 w2 = *(const ulonglong2*)&Wsd[kk][128 + ty * 8];
            ulonglong2 w3 = *(const ulonglong2*)&Wsd[kk][128 + ty * 8 + 4];
            u64 xp[4] = { xa.x, xa.y, xb.x, xb.y };
            u64 wp[8] = { w0.x, w0.y, w1.x, w1.y, w2.x, w2.y, w3.x, w3.y };
            #pragma unroll
            for (int i = 0; i < 8; ++i)
                #pragma unroll
                for (int j = 0; j < 4; ++j)
                    acc[i][j] = fma2(wp[i], xp[j], acc[i][j]);
        }
        __syncthreads();
    }

    // epilogue: BN(eval, running stats unit) + ReLU, then store
    const float BNS = 1.0f / sqrtf(1.0f + 1e-5f);
    float vals[8][8];   // [i over o][q over n]
    #pragma unroll
    for (int gi = 0; gi < 2; ++gi) {
        #pragma unroll
        for (int ii = 0; ii < 4; ++ii) {
            int i = gi * 4 + ii;
            int o = o0 + gi * 64 + ty * 4 + ii;
            float sc = __ldg(gamma + o) * BNS;
            float bb = sc * __ldg(bias + o) + __ldg(beta + o);
            float v[8];
            unpack2(acc[i][0], v[0], v[1]);
            unpack2(acc[i][1], v[2], v[3]);
            unpack2(acc[i][2], v[4], v[5]);
            unpack2(acc[i][3], v[6], v[7]);
            #pragma unroll
            for (int q = 0; q < 8; ++q) vals[i][q] = fmaxf(sc * v[q] + bb, 0.f);
        }
    }
    if (!pm_out) {
        // channel-major: Y[o][n], coalesced float4 along n
        #pragma unroll
        for (int gi = 0; gi < 2; ++gi)
            #pragma unroll
            for (int ii = 0; ii < 4; ++ii) {
                int i = gi * 4 + ii;
                int o = o0 + gi * 64 + ty * 4 + ii;
                float4 a = { vals[i][0], vals[i][1], vals[i][2], vals[i][3] };
                float4 c = { vals[i][4], vals[i][5], vals[i][6], vals[i][7] };
                *(float4*)(Yb + (size_t)o * N + n0 + tx * 4)      = a;
                *(float4*)(Yb + (size_t)o * N + n0 + 64 + tx * 4) = c;
            }
    } else {
        // point-major: Y[n][o], float4 along o (4 consecutive o per thread group)
        #pragma unroll
        for (int gi = 0; gi < 2; ++gi)
            #pragma unroll
            for (int q = 0; q < 8; ++q) {
                int n = n0 + ((q < 4) ? (tx * 4 + q) : (64 + tx * 4 + (q - 4)));
                float4 a = { vals[gi*4+0][q], vals[gi*4+1][q],
                             vals[gi*4+2][q], vals[gi*4+3][q] };
                *(float4*)(Yb + (size_t)n * O + o0 + gi * 64 + ty * 4) = a;
            }
    }
}

// ---------------------------------------------------------------------------
extern "C" void kernel_launch(void* const* d_in, const int* in_sizes, int n_in,
                              void* d_out, int out_size)
{
    const float* radar = (const float*)d_in[0];
    const float* l1f   = (const float*)d_in[1];
    const float* l2f   = (const float*)d_in[2];
    const float* l0_l1 = (const float*)d_in[3];
    const float* l1_l2 = (const float*)d_in[4];
    const float* w21a  = (const float*)d_in[5];
    const float* b21a  = (const float*)d_in[6];
    const float* g21a  = (const float*)d_in[7];
    const float* be21a = (const float*)d_in[8];
    const float* w21b  = (const float*)d_in[9];
    const float* b21b  = (const float*)d_in[10];
    const float* g21b  = (const float*)d_in[11];
    const float* be21b = (const float*)d_in[12];
    const float* w10a  = (const float*)d_in[13];
    const float* b10a  = (const float*)d_in[14];
    const float* g10a  = (const float*)d_in[15];
    const float* be10a = (const float*)d_in[16];
    const float* w10b  = (const float*)d_in[17];
    const float* b10b  = (const float*)d_in[18];
    const float* g10b  = (const float*)d_in[19];
    const float* be10b = (const float*)d_in[20];

    float *x1, *y1, *f, *x3, *y3;
    cudaGetSymbolAddress((void**)&x1, g_X1);
    cudaGetSymbolAddress((void**)&y1, g_Y1);
    cudaGetSymbolAddress((void**)&f,  g_F);
    cudaGetSymbolAddress((void**)&x3, g_X3);
    cudaGetSymbolAddress((void**)&y3, g_Y3);

    // level 2 -> 1 interpolation + concat
    knn_build_x1<<<dim3(N1_/256, B_), 256>>>(l1_l2, l1f, l2f, x1);
    // mlp_2_1: 320 -> 640 -> 640  (point-major outputs)
    gemm_bn_relu<<<dim3(N1_/128, 640/128, B_), 256>>>(w21a, x1, y1, b21a, g21a, be21a, 320, N1_, 640, 1);
    gemm_bn_relu<<<dim3(N1_/128, 640/128, B_), 256>>>(w21b, y1, f,  b21b, g21b, be21b, 640, N1_, 640, 1);
    // level 1 -> 0 interpolation + concat with radar
    knn_build_x3<<<dim3(N0_/256, B_), 256>>>(l0_l1, radar, f, x3);
    // mlp_1_0: 704 -> 640 -> 768 ; final GEMM writes channel-major d_out
    gemm_bn_relu<<<dim3(N0_/128, 640/128, B_), 256>>>(w10a, x3, y3, b10a, g10a, be10a, 704, N0_, 640, 1);
    gemm_bn_relu<<<dim3(N0_/128, 768/128, B_), 256>>>(w10b, y3, (float*)d_out, b10b, g10b, be10b, 640, N0_, 768, 0);
}

// round 4
// speedup vs baseline: 1.4559x; 1.4559x over previous
#include <cuda_runtime.h>
#include <cuda_bf16.h>
#include <cstddef>

// ---------------------------------------------------------------------------
// FeaturePropogate, restructured:
//   W*concat(feat, interp(F)) == W_feat*feat + interp(W_F * F)
// so the first layer of each MLP block is computed at the COARSE resolution
// and gathered afterwards. GEMMs are NT, fp32 packed fma.rn.f32x2, double-
// buffered shared tiles. KNN top-8 uses 4 threads/point + sorted 4-way merge.
// ---------------------------------------------------------------------------

#define B_     4
#define N0_    8192
#define N1_    2048
#define N2_    512

// scratch (device globals: allocation is forbidden)
__device__ float g_G2[(size_t)B_ * N2_ * 640];   // W21a_f2 * l2_feat   (pm)
__device__ float g_H1[(size_t)B_ * N1_ * 640];   // W21a_l1 * l1_feat   (pm)
__device__ float g_Y1[(size_t)B_ * N1_ * 640];   // layer 21a out       (pm)
__device__ float g_F [(size_t)B_ * N1_ * 640];   // layer 21b out       (pm)
__device__ float g_G [(size_t)B_ * N1_ * 640];   // W10a_F * F          (pm)
__device__ float g_Hr[(size_t)B_ * N0_ * 640];   // W10a_r * radar      (pm)
__device__ float g_Y3[(size_t)B_ * N0_ * 640];   // layer 10a out       (pm)
__device__ int   g_i1[(size_t)B_ * N1_ * 8];
__device__ float g_w1[(size_t)B_ * N1_ * 8];
__device__ int   g_i0[(size_t)B_ * N0_ * 8];
__device__ float g_w0[(size_t)B_ * N0_ * 8];

typedef unsigned long long u64;

__device__ __forceinline__ u64 fma2(u64 a, u64 b, u64 c) {
    u64 d;
    asm("fma.rn.f32x2 %0, %1, %2, %3;" : "=l"(d) : "l"(a), "l"(b), "l"(c));
    return d;
}
__device__ __forceinline__ void unpack2(u64 v, float& lo, float& hi) {
    asm("mov.b64 {%0, %1}, %2;" : "=f"(lo), "=f"(hi) : "l"(v));
}

// ---------------------------------------------------------------------------
// KNN top-8: D is [B][M][Npts]; point n reads column n (coalesced across n).
// 256 threads = 64 points x 4 segments; per-thread sorted top-8 over M/4,
// then a 4-way sorted merge by one thread per point. Outputs idx + normalized
// inverse-distance weights.
// ---------------------------------------------------------------------------
__global__ __launch_bounds__(256)
void knn_topk(const float* __restrict__ D, int M, int Npts,
              int* __restrict__ out_i, float* __restrict__ out_w)
{
    __shared__ float sd[64][4][8];
    __shared__ int   si[64][4][8];
    const int b   = blockIdx.y;
    const int p   = threadIdx.x & 63;
    const int q   = threadIdx.x >> 6;
    const int n   = blockIdx.x * 64 + p;
    const int seg = M >> 2;

    float bd[8]; int bi[8];
    #pragma unroll
    for (int j = 0; j < 8; ++j) { bd[j] = 3.4e38f; bi[j] = 0; }
    const float* col = D + (size_t)b * M * Npts + n + (size_t)(q * seg) * Npts;
    #pragma unroll 8
    for (int m = 0; m < seg; ++m) {
        float v = __ldg(col + (size_t)m * Npts);
        if (v < bd[7]) {
            bd[7] = v; bi[7] = q * seg + m;
            #pragma unroll
            for (int r = 7; r >= 1; --r) {
                if (bd[r] < bd[r-1]) {
                    float td = bd[r]; bd[r] = bd[r-1]; bd[r-1] = td;
                    int   ti = bi[r]; bi[r] = bi[r-1]; bi[r-1] = ti;
                }
            }
        }
    }
    #pragma unroll
    for (int j = 0; j < 8; ++j) { sd[p][q][j] = bd[j]; si[p][q][j] = bi[j]; }
    __syncthreads();

    if (threadIdx.x < 64) {
        const int pp = threadIdx.x;
        int p0 = 0, p1 = 0, p2 = 0, p3 = 0;
        float d8[8]; int i8[8];
        #pragma unroll
        for (int k = 0; k < 8; ++k) {
            float v0 = sd[pp][0][p0], v1 = sd[pp][1][p1];
            float v2 = sd[pp][2][p2], v3 = sd[pp][3][p3];
            float m01 = v0; int q01 = 0; if (v1 < m01) { m01 = v1; q01 = 1; }
            float m23 = v2; int q23 = 2; if (v3 < m23) { m23 = v3; q23 = 3; }
            float mv = m01; int qq = q01; if (m23 < m01) { mv = m23; qq = q23; }
            d8[k] = mv;
            if      (qq == 0) i8[k] = si[pp][0][p0++];
            else if (qq == 1) i8[k] = si[pp][1][p1++];
            else if (qq == 2) i8[k] = si[pp][2][p2++];
            else              i8[k] = si[pp][3][p3++];
        }
        float w[8], s = 0.f;
        #pragma unroll
        for (int j = 0; j < 8; ++j) { w[j] = 1.f / (d8[j] + 1e-8f); s += w[j]; }
        float inv = 1.f / (s + 1e-8f);
        const int nn = blockIdx.x * 64 + pp;
        size_t base = ((size_t)b * Npts + nn) * 8;
        #pragma unroll
        for (int j = 0; j < 8; ++j) { out_i[base + j] = i8[j]; out_w[base + j] = w[j] * inv; }
    }
}

// ---------------------------------------------------------------------------
// combine: Y[n] = ReLU( sc*(H[n] + sum_j w_j G[idx_j] ) + bb ), all point-major
// warp per point, lane handles channels lane+32r (640 channels -> r<20).
// ---------------------------------------------------------------------------
__global__ __launch_bounds__(256)
void combine_bn_relu(const float* __restrict__ H,    // [B][Np][640]
                     const float* __restrict__ G,    // [B][Ng][640]
                     const int*   __restrict__ knn_i,
                     const float* __restrict__ knn_w,
                     const float* __restrict__ bias,
                     const float* __restrict__ gamma,
                     const float* __restrict__ beta,
                     float* __restrict__ Y, int Np, int Ng)
{
    __shared__ float s_sc[640], s_bb[640];
    const float BNS = 0.99999500003749968f;   // 1/sqrt(1+1e-5)
    for (int c = threadIdx.x; c < 640; c += 256) {
        float sc = __ldg(gamma + c) * BNS;
        s_sc[c] = sc;
        s_bb[c] = sc * __ldg(bias + c) + __ldg(beta + c);
    }
    __syncthreads();
    const int b    = blockIdx.y;
    const int warp = threadIdx.x >> 5, lane = threadIdx.x & 31;
    const int n    = blockIdx.x * 8 + warp;
    const size_t pbase = (size_t)b * Np + n;

    int idx[8]; float w8[8];
    const int*   ip = knn_i + pbase * 8;
    const float* wp = knn_w + pbase * 8;
    #pragma unroll
    for (int j = 0; j < 8; ++j) { idx[j] = __ldg(ip + j); w8[j] = __ldg(wp + j); }

    const float* h = H + pbase * 640;
    float acc[20];
    #pragma unroll
    for (int r = 0; r < 20; ++r) acc[r] = __ldg(h + lane + 32 * r);
    #pragma unroll
    for (int j = 0; j < 8; ++j) {
        const float* g = G + ((size_t)b * Ng + idx[j]) * 640;
        const float wj = w8[j];
        #pragma unroll
        for (int r = 0; r < 20; ++r) acc[r] += wj * __ldg(g + lane + 32 * r);
    }
    float* y = Y + pbase * 640;
    #pragma unroll
    for (int r = 0; r < 20; ++r) {
        int c = lane + 32 * r;
        y[c] = fmaxf(s_sc[c] * acc[r] + s_bb[c], 0.f);
    }
}

// ---------------------------------------------------------------------------
// GEMM  Y[o][n] = sum_k W[o][k+koff]*X[n][k]   (W row stride = ldW)
// 128(O) x 128(N) x 16(K) tiles, 256 threads, 8x8 microtile, fma.rn.f32x2,
// double-buffered shared tiles with register-staged prefetch.
// mode: 0 = channel-major out + BN+ReLU, 1 = point-major out + BN+ReLU,
//       2 = point-major raw (no bias / BN / activation).
// ---------------------------------------------------------------------------
__global__ __launch_bounds__(256, 2)
void gemm_dx(const float* __restrict__ W, int ldW,
             const float* __restrict__ X,      // [B][N][K]
             float* __restrict__ Y,
             const float* __restrict__ bias,
             const float* __restrict__ gamma,
             const float* __restrict__ beta,
             int K, int N, int O, int mode)
{
    __shared__ float Wsd[2][16][256];  // duplicated (w,w) pairs
    __shared__ float Xs [2][16][128];

    const int b  = blockIdx.z;
    const float* Xb = X + (size_t)b * N * K;
    float*       Yb = Y + (size_t)b * N * O;
    const int o0 = blockIdx.y * 128;
    const int n0 = blockIdx.x * 128;
    const int t  = threadIdx.x;
    const int tx = t & 15;
    const int ty = t >> 4;

    u64 acc[8][4];
    #pragma unroll
    for (int i = 0; i < 8; ++i)
        #pragma unroll
        for (int j = 0; j < 4; ++j) acc[i][j] = 0ull;

    float4 wr[2], xr[2];
    auto load_tiles = [&](int k0) {
        #pragma unroll
        for (int r = 0; r < 2; ++r) {
            int idx = t + r * 256;
            int row = idx >> 2, kc = idx & 3;
            wr[r] = *(const float4*)(W + (size_t)(o0 + row) * ldW + k0 + kc * 4);
            xr[r] = *(const float4*)(Xb + (size_t)(n0 + row) * K + k0 + kc * 4);
        }
    };
    auto store_tiles = [&](int buf) {
        #pragma unroll
        for (int r = 0; r < 2; ++r) {
            int idx = t + r * 256;
            int row = idx >> 2, kc = idx & 3;
            float4 wv = wr[r];
            Wsd[buf][kc*4+0][2*row] = wv.x; Wsd[buf][kc*4+0][2*row+1] = wv.x;
            Wsd[buf][kc*4+1][2*row] = wv.y; Wsd[buf][kc*4+1][2*row+1] = wv.y;
            Wsd[buf][kc*4+2][2*row] = wv.z; Wsd[buf][kc*4+2][2*row+1] = wv.z;
            Wsd[buf][kc*4+3][2*row] = wv.w; Wsd[buf][kc*4+3][2*row+1] = wv.w;
            float4 xv = xr[r];
            Xs[buf][kc*4+0][row] = xv.x;
            Xs[buf][kc*4+1][row] = xv.y;
            Xs[buf][kc*4+2][row] = xv.z;
            Xs[buf][kc*4+3][row] = xv.w;
        }
    };

    load_tiles(0);
    store_tiles(0);
    __syncthreads();

    const int nt = K >> 4;
    for (int it = 0; it < nt; ++it) {
        const int cur = it & 1;
        if (it + 1 < nt) load_tiles((it + 1) << 4);
        #pragma unroll
        for (int kk = 0; kk < 16; ++kk) {
            ulonglong2 xa = *(const ulonglong2*)&Xs[cur][kk][tx * 4];
            ulonglong2 xb = *(const ulonglong2*)&Xs[cur][kk][64 + tx * 4];
            ulonglong2 w0 = *(const ulonglong2*)&Wsd[cur][kk][ty * 8];
            ulonglong2 w1 = *(const ulonglong2*)&Wsd[cur][kk][ty * 8 + 4];
            ulonglong2 w2 = *(const ulonglong2*)&Wsd[cur][kk][128 + ty * 8];
            ulonglong2 w3 = *(const ulonglong2*)&Wsd[cur][kk][128 + ty * 8 + 4];
            u64 xp[4] = { xa.x, xa.y, xb.x, xb.y };
            u64 wp[8] = { w0.x, w0.y, w1.x, w1.y, w2.x, w2.y, w3.x, w3.y };
            #pragma unroll
            for (int i = 0; i < 8; ++i)
                #pragma unroll
                for (int j = 0; j < 4; ++j)
                    acc[i][j] = fma2(wp[i], xp[j], acc[i][j]);
        }
        if (it + 1 < nt) store_tiles(cur ^ 1);
        __syncthreads();
    }

    // epilogue
    float vals[8][8];   // [i over o][q over n]
    #pragma unroll
    for (int gi = 0; gi < 2; ++gi) {
        #pragma unroll
        for (int ii = 0; ii < 4; ++ii) {
            int i = gi * 4 + ii;
            float v[8];
            unpack2(acc[i][0], v[0], v[1]);
            unpack2(acc[i][1], v[2], v[3]);
            unpack2(acc[i][2], v[4], v[5]);
            unpack2(acc[i][3], v[6], v[7]);
            if (mode == 2) {
                #pragma unroll
                for (int qq = 0; qq < 8; ++qq) vals[i][qq] = v[qq];
            } else {
                const float BNS = 0.99999500003749968f;
                int o = o0 + gi * 64 + ty * 4 + ii;
                float sc = __ldg(gamma + o) * BNS;
                float bb = sc * __ldg(bias + o) + __ldg(beta + o);
                #pragma unroll
                for (int qq = 0; qq < 8; ++qq) vals[i][qq] = fmaxf(sc * v[qq] + bb, 0.f);
            }
        }
    }
    if (mode == 0) {
        // channel-major: Y[o][n]
        #pragma unroll
        for (int gi = 0; gi < 2; ++gi)
            #pragma unroll
            for (int ii = 0; ii < 4; ++ii) {
                int i = gi * 4 + ii;
                int o = o0 + gi * 64 + ty * 4 + ii;
                float4 a = { vals[i][0], vals[i][1], vals[i][2], vals[i][3] };
                float4 c = { vals[i][4], vals[i][5], vals[i][6], vals[i][7] };
                *(float4*)(Yb + (size_t)o * N + n0 + tx * 4)      = a;
                *(float4*)(Yb + (size_t)o * N + n0 + 64 + tx * 4) = c;
            }
    } else {
        // point-major: Y[n][o]
        #pragma unroll
        for (int gi = 0; gi < 2; ++gi)
            #pragma unroll
            for (int qq = 0; qq < 8; ++qq) {
                int n = n0 + ((qq < 4) ? (tx * 4 + qq) : (64 + tx * 4 + (qq - 4)));
                float4 a = { vals[gi*4+0][qq], vals[gi*4+1][qq],
                             vals[gi*4+2][qq], vals[gi*4+3][qq] };
                *(float4*)(Yb + (size_t)n * O + o0 + gi * 64 + ty * 4) = a;
            }
    }
}

// ---------------------------------------------------------------------------
extern "C" void kernel_launch(void* const* d_in, const int* in_sizes, int n_in,
                              void* d_out, int out_size)
{
    const float* radar = (const float*)d_in[0];
    const float* l1f   = (const float*)d_in[1];
    const float* l2f   = (const float*)d_in[2];
    const float* l0_l1 = (const float*)d_in[3];
    const float* l1_l2 = (const float*)d_in[4];
    const float* w21a  = (const float*)d_in[5];
    const float* b21a  = (const float*)d_in[6];
    const float* g21a  = (const float*)d_in[7];
    const float* be21a = (const float*)d_in[8];
    const float* w21b  = (const float*)d_in[9];
    const float* b21b  = (const float*)d_in[10];
    const float* g21b  = (const float*)d_in[11];
    const float* be21b = (const float*)d_in[12];
    const float* w10a  = (const float*)d_in[13];
    const float* b10a  = (const float*)d_in[14];
    const float* g10a  = (const float*)d_in[15];
    const float* be10a = (const float*)d_in[16];
    const float* w10b  = (const float*)d_in[17];
    const float* b10b  = (const float*)d_in[18];
    const float* g10b  = (const float*)d_in[19];
    const float* be10b = (const float*)d_in[20];

    float *G2, *H1, *Y1, *F, *G, *Hr, *Y3, *w1, *w0;
    int *i1, *i0;
    cudaGetSymbolAddress((void**)&G2, g_G2);
    cudaGetSymbolAddress((void**)&H1, g_H1);
    cudaGetSymbolAddress((void**)&Y1, g_Y1);
    cudaGetSymbolAddress((void**)&F,  g_F);
    cudaGetSymbolAddress((void**)&G,  g_G);
    cudaGetSymbolAddress((void**)&Hr, g_Hr);
    cudaGetSymbolAddress((void**)&Y3, g_Y3);
    cudaGetSymbolAddress((void**)&i1, g_i1);
    cudaGetSymbolAddress((void**)&w1, g_w1);
    cudaGetSymbolAddress((void**)&i0, g_i0);
    cudaGetSymbolAddress((void**)&w0, g_w0);

    // KNN selections (independent of GEMMs up front)
    knn_topk<<<dim3(N1_/64, B_), 256>>>(l1_l2, N2_, N1_, i1, w1);
    knn_topk<<<dim3(N0_/64, B_), 256>>>(l0_l1, N1_, N0_, i0, w0);

    // level 2->1: G2 = W21a[:,128:320] * l2_feat ; H1 = W21a[:,0:128] * l1_feat
    gemm_dx<<<dim3(N2_/128, 640/128, B_), 256>>>(w21a + 128, 320, l2f, G2,
                                                 nullptr, nullptr, nullptr, 192, N2_, 640, 2);
    gemm_dx<<<dim3(N1_/128, 640/128, B_), 256>>>(w21a, 320, l1f, H1,
                                                 nullptr, nullptr, nullptr, 128, N1_, 640, 2);
    combine_bn_relu<<<dim3(N1_/8, B_), 256>>>(H1, G2, i1, w1, b21a, g21a, be21a, Y1, N1_, N2_);
    // layer 21b
    gemm_dx<<<dim3(N1_/128, 640/128, B_), 256>>>(w21b, 640, Y1, F,
                                                 b21b, g21b, be21b, 640, N1_, 640, 1);
    // level 1->0: G = W10a[:,64:704] * F ; Hr = W10a[:,0:64] * radar
    gemm_dx<<<dim3(N1_/128, 640/128, B_), 256>>>(w10a + 64, 704, F, G,
                                                 nullptr, nullptr, nullptr, 640, N1_, 640, 2);
    gemm_dx<<<dim3(N0_/128, 640/128, B_), 256>>>(w10a, 704, radar, Hr,
                                                 nullptr, nullptr, nullptr, 64, N0_, 640, 2);
    combine_bn_relu<<<dim3(N0_/8, B_), 256>>>(Hr, G, i0, w0, b10a, g10a, be10a, Y3, N0_, N1_);
    // layer 10b -> channel-major output
    gemm_dx<<<dim3(N0_/128, 768/128, B_), 256>>>(w10b, 640, Y3, (float*)d_out,
                                                 b10b, g10b, be10b, 640, N0_, 768, 0);
}

// round 7
// speedup vs baseline: 2.3500x; 1.6141x over previous
#include <cuda_runtime.h>
#include <cuda_bf16.h>
#include <cstdint>
#include <cstddef>

// ---------------------------------------------------------------------------
// FeaturePropogate via mma.sync bf16 (plain sm_103 PTX):
//   - interp pushed through first MLP layer (W*concat == W_a*feat + interp(W_b*F))
//   - GEMMs: 3-term error-compensated bf16 mma.sync (AhBh + AhBl + AlBh), fp32 acc
//   - inputs split to bf16 hi/lo planes exactly once
//   - cp.async double-buffered smem, ldmatrix fragments, smem-transposed epilogue
// ---------------------------------------------------------------------------

#define B_     4
#define N0_    8192
#define N1_    2048
#define N2_    512

// ---- device scratch (no allocation allowed) ----
__device__ __nv_bfloat16 g_l1h[(size_t)B_*N1_*128], g_l1l[(size_t)B_*N1_*128];
__device__ __nv_bfloat16 g_l2h[(size_t)B_*N2_*192], g_l2l[(size_t)B_*N2_*192];
__device__ __nv_bfloat16 g_rdh[(size_t)B_*N0_*64],  g_rdl[(size_t)B_*N0_*64];
__device__ __nv_bfloat16 g_w21ah[640*320], g_w21al[640*320];
__device__ __nv_bfloat16 g_w21bh[640*640], g_w21bl[640*640];
__device__ __nv_bfloat16 g_w10ah[640*704], g_w10al[640*704];
__device__ __nv_bfloat16 g_w10bh[768*640], g_w10bl[768*640];
__device__ __nv_bfloat16 g_Y1h[(size_t)B_*N1_*640], g_Y1l[(size_t)B_*N1_*640];
__device__ __nv_bfloat16 g_Fh [(size_t)B_*N1_*640], g_Fl [(size_t)B_*N1_*640];
__device__ __nv_bfloat16 g_Y3h[(size_t)B_*N0_*640], g_Y3l[(size_t)B_*N0_*640];
__device__ float g_G2[(size_t)B_*N2_*640];
__device__ float g_H1[(size_t)B_*N1_*640];
__device__ float g_G [(size_t)B_*N1_*640];
__device__ float g_Hr[(size_t)B_*N0_*640];
__device__ int   g_i1[(size_t)B_*N1_*8];
__device__ float g_w1[(size_t)B_*N1_*8];
__device__ int   g_i0[(size_t)B_*N0_*8];
__device__ float g_w0[(size_t)B_*N0_*8];

__device__ __forceinline__ uint32_t smem_u32_of(const void* p) {
    uint32_t a;
    asm("{ .reg .u64 t; cvta.to.shared.u64 t, %1; cvt.u32.u64 %0, t; }" : "=r"(a) : "l"(p));
    return a;
}
__device__ __forceinline__ void ldsm4(uint32_t* r, uint32_t addr) {
    asm volatile("ldmatrix.sync.aligned.m8n8.x4.shared.b16 {%0,%1,%2,%3}, [%4];"
                 : "=r"(r[0]), "=r"(r[1]), "=r"(r[2]), "=r"(r[3]) : "r"(addr));
}
__device__ __forceinline__ void mma16816(float* d, const uint32_t* a, const uint32_t* b) {
    asm volatile(
        "mma.sync.aligned.m16n8k16.row.col.f32.bf16.bf16.f32 "
        "{%0,%1,%2,%3}, {%4,%5,%6,%7}, {%8,%9}, {%0,%1,%2,%3};"
        : "+f"(d[0]), "+f"(d[1]), "+f"(d[2]), "+f"(d[3])
        : "r"(a[0]), "r"(a[1]), "r"(a[2]), "r"(a[3]), "r"(b[0]), "r"(b[1]));
}
__device__ __forceinline__ void cp16(uint32_t saddr, const void* gaddr) {
    asm volatile("cp.async.cg.shared.global [%0], [%1], 16;" :: "r"(saddr), "l"(gaddr));
}

// ---------------------------------------------------------------------------
// KNN top-8 (verified R3). D: [B][M][Npts], point n reads column n.
// ---------------------------------------------------------------------------
__global__ __launch_bounds__(256)
void knn_topk(const float* __restrict__ D, int M, int Npts,
              int* __restrict__ out_i, float* __restrict__ out_w)
{
    __shared__ float sd[64][4][8];
    __shared__ int   si[64][4][8];
    const int b   = blockIdx.y;
    const int p   = threadIdx.x & 63;
    const int q   = threadIdx.x >> 6;
    const int n   = blockIdx.x * 64 + p;
    const int seg = M >> 2;

    float bd[8]; int bi[8];
    #pragma unroll
    for (int j = 0; j < 8; ++j) { bd[j] = 3.4e38f; bi[j] = 0; }
    const float* col = D + (size_t)b * M * Npts + n + (size_t)(q * seg) * Npts;
    #pragma unroll 8
    for (int m = 0; m < seg; ++m) {
        float v = __ldg(col + (size_t)m * Npts);
        if (v < bd[7]) {
            bd[7] = v; bi[7] = q * seg + m;
            #pragma unroll
            for (int r = 7; r >= 1; --r) {
                if (bd[r] < bd[r-1]) {
                    float td = bd[r]; bd[r] = bd[r-1]; bd[r-1] = td;
                    int   ti = bi[r]; bi[r] = bi[r-1]; bi[r-1] = ti;
                }
            }
        }
    }
    #pragma unroll
    for (int j = 0; j < 8; ++j) { sd[p][q][j] = bd[j]; si[p][q][j] = bi[j]; }
    __syncthreads();

    if (threadIdx.x < 64) {
        const int pp = threadIdx.x;
        int p0 = 0, p1 = 0, p2 = 0, p3 = 0;
        float d8[8]; int i8[8];
        #pragma unroll
        for (int k = 0; k < 8; ++k) {
            float v0 = sd[pp][0][p0], v1 = sd[pp][1][p1];
            float v2 = sd[pp][2][p2], v3 = sd[pp][3][p3];
            float m01 = v0; int q01 = 0; if (v1 < m01) { m01 = v1; q01 = 1; }
            float m23 = v2; int q23 = 2; if (v3 < m23) { m23 = v3; q23 = 3; }
            float mv = m01; int qq = q01; if (m23 < m01) { mv = m23; qq = q23; }
            d8[k] = mv;
            if      (qq == 0) i8[k] = si[pp][0][p0++];
            else if (qq == 1) i8[k] = si[pp][1][p1++];
            else if (qq == 2) i8[k] = si[pp][2][p2++];
            else              i8[k] = si[pp][3][p3++];
        }
        float w[8], s = 0.f;
        #pragma unroll
        for (int j = 0; j < 8; ++j) { w[j] = 1.f / (d8[j] + 1e-8f); s += w[j]; }
        float inv = 1.f / (s + 1e-8f);
        const int nn = blockIdx.x * 64 + pp;
        size_t base = ((size_t)b * Npts + nn) * 8;
        #pragma unroll
        for (int j = 0; j < 8; ++j) { out_i[base + j] = i8[j]; out_w[base + j] = w[j] * inv; }
    }
}

// ---------------------------------------------------------------------------
// convert fp32 -> bf16 hi/lo planes
// ---------------------------------------------------------------------------
__global__ __launch_bounds__(256)
void cvt_hilo(const float* __restrict__ x, __nv_bfloat16* __restrict__ hi,
              __nv_bfloat16* __restrict__ lo, int n4)
{
    int i = blockIdx.x * 256 + threadIdx.x;
    if (i >= n4) return;
    float4 v = ((const float4*)x)[i];
    __nv_bfloat16 h0 = __float2bfloat16(v.x), h1 = __float2bfloat16(v.y);
    __nv_bfloat16 h2 = __float2bfloat16(v.z), h3 = __float2bfloat16(v.w);
    __nv_bfloat16 l0 = __float2bfloat16(v.x - __bfloat162float(h0));
    __nv_bfloat16 l1 = __float2bfloat16(v.y - __bfloat162float(h1));
    __nv_bfloat16 l2 = __float2bfloat16(v.z - __bfloat162float(h2));
    __nv_bfloat16 l3 = __float2bfloat16(v.w - __bfloat162float(h3));
    ((__nv_bfloat162*)hi)[i*2+0] = __nv_bfloat162(h0, h1);
    ((__nv_bfloat162*)hi)[i*2+1] = __nv_bfloat162(h2, h3);
    ((__nv_bfloat162*)lo)[i*2+0] = __nv_bfloat162(l0, l1);
    ((__nv_bfloat162*)lo)[i*2+1] = __nv_bfloat162(l2, l3);
}

// ---------------------------------------------------------------------------
// combine: v = ReLU(sc*(H[n] + sum_j w_j G[idx_j]) + bb) -> bf16 hi/lo planes
// ---------------------------------------------------------------------------
__global__ __launch_bounds__(256)
void combine_bn_relu(const float* __restrict__ H,    // [B][Np][640]
                     const float* __restrict__ G,    // [B][Ng][640]
                     const int*   __restrict__ knn_i,
                     const float* __restrict__ knn_w,
                     const float* __restrict__ bias,
                     const float* __restrict__ gamma,
                     const float* __restrict__ beta,
                     __nv_bfloat16* __restrict__ Yh,
                     __nv_bfloat16* __restrict__ Yl, int Np, int Ng)
{
    __shared__ float s_sc[640], s_bb[640];
    const float BNS = 0.99999500003749968f;   // 1/sqrt(1+1e-5)
    for (int c = threadIdx.x; c < 640; c += 256) {
        float sc = __ldg(gamma + c) * BNS;
        s_sc[c] = sc;
        s_bb[c] = sc * __ldg(bias + c) + __ldg(beta + c);
    }
    __syncthreads();
    const int b    = blockIdx.y;
    const int warp = threadIdx.x >> 5, lane = threadIdx.x & 31;
    const int n    = blockIdx.x * 8 + warp;
    const size_t pbase = (size_t)b * Np + n;

    int idx[8]; float w8[8];
    const int*   ip = knn_i + pbase * 8;
    const float* wp = knn_w + pbase * 8;
    #pragma unroll
    for (int j = 0; j < 8; ++j) { idx[j] = __ldg(ip + j); w8[j] = __ldg(wp + j); }

    const float* h = H + pbase * 640;
    float acc[20];
    #pragma unroll
    for (int r = 0; r < 20; ++r) acc[r] = __ldg(h + lane + 32 * r);
    #pragma unroll
    for (int j = 0; j < 8; ++j) {
        const float* g = G + ((size_t)b * Ng + idx[j]) * 640;
        const float wj = w8[j];
        #pragma unroll
        for (int r = 0; r < 20; ++r) acc[r] += wj * __ldg(g + lane + 32 * r);
    }
    #pragma unroll
    for (int r = 0; r < 20; ++r) {
        int c = lane + 32 * r;
        float v = fmaxf(s_sc[c] * acc[r] + s_bb[c], 0.f);
        __nv_bfloat16 hh = __float2bfloat16(v);
        Yh[pbase * 640 + c] = hh;
        Yl[pbase * 640 + c] = __float2bfloat16(v - __bfloat162float(hh));
    }
}

// ---------------------------------------------------------------------------
// mma.sync GEMM:  D[o][n] = sum_k W[o][k] * X[n][k]  (K-major bf16 hi/lo)
// 3-term compensation, fp32 accum. Block tile 128(o) x 128(n), K-chunk 32,
// 512 threads = 4x4 warps, warp tile 32x32. cp.async double-buffered smem,
// padded stride 40 bf16 (LDSM conflict-free). Epilogue through smem.
// mode: 0 = channel-major fp32 + BN+ReLU
//       1 = point-major bf16 hi/lo + BN+ReLU
//       2 = point-major fp32 raw
// ---------------------------------------------------------------------------
#define STAGE_BYTES 40960              // 4 planes x 128 x 40 bf16
#define GEMM_SMEM   (2 * STAGE_BYTES)  // 81920; epilogue (67584 B) reuses it

__global__ __launch_bounds__(512)
void gemm_mma(const __nv_bfloat16* __restrict__ Wh, const __nv_bfloat16* __restrict__ Wl, int ldW,
              const __nv_bfloat16* __restrict__ Xh, const __nv_bfloat16* __restrict__ Xl,
              float* __restrict__ Yf,
              __nv_bfloat16* __restrict__ Yh, __nv_bfloat16* __restrict__ Yl,
              const float* __restrict__ bias, const float* __restrict__ gamma,
              const float* __restrict__ beta,
              int K, int N, int O, int mode)
{
    extern __shared__ char dsm[];
    const uint32_t sbase = smem_u32_of(dsm);
    const int t = threadIdx.x, lane = t & 31, w = t >> 5;
    const int wm = w >> 2, wn = w & 3;
    const int b  = blockIdx.z;
    const int n0 = blockIdx.x * 128;
    const int o0 = blockIdx.y * 128;

    const __nv_bfloat16* srcs[4];
    srcs[0] = Wh + (size_t)o0 * ldW;
    srcs[1] = Wl + (size_t)o0 * ldW;
    srcs[2] = Xh + ((size_t)b * N + n0) * K;
    srcs[3] = Xl + ((size_t)b * N + n0) * K;
    int lds[4] = { ldW, ldW, K, K };

    float acc[2][4][4];
    #pragma unroll
    for (int i = 0; i < 2; ++i)
        #pragma unroll
        for (int j = 0; j < 4; ++j)
            #pragma unroll
            for (int e = 0; e < 4; ++e) acc[i][j][e] = 0.f;

    // stage loader: 4 planes x 128 rows x 32 cols bf16, padded stride 40.
    // 128 rows x 4 chunks = 512 cp16 per plane = ONE per thread per plane.
    const int ld_row = t >> 2;        // 0..127
    const int ld_c4  = t & 3;         // 0..3 (16B chunks)
    auto cp_stage = [&](int k0, int buf) {
        uint32_t sb = sbase + buf * STAGE_BYTES + ld_row * 80 + ld_c4 * 16;
        #pragma unroll
        for (int pl = 0; pl < 4; ++pl) {
            cp16(sb + pl * 10240,
                 srcs[pl] + (size_t)ld_row * lds[pl] + k0 + ld_c4 * 8);
        }
        asm volatile("cp.async.commit_group;" ::: "memory");
    };

    const int g = lane >> 3;
    const int arow_off = (g & 1) * 8 + (lane & 7);      // A: g0/g1 rows 0-15
    const int acol_off = (g >> 1) * 8;                  //    g2/g3 k+8
    const int brow_off = (g >> 1) * 8 + (lane & 7);     // B: g0/g1 n 0-7, g2/g3 n+8
    const int bcol_off = (g & 1) * 8;                   //    g1/g3 k+8

    const int nc = K >> 5;
    cp_stage(0, 0);
    for (int it = 0; it < nc; ++it) {
        if (it + 1 < nc) {
            cp_stage((it + 1) << 5, (it + 1) & 1);
            asm volatile("cp.async.wait_group 1;" ::: "memory");
        } else {
            asm volatile("cp.async.wait_group 0;" ::: "memory");
        }
        __syncthreads();

        const uint32_t pAh = sbase + (it & 1) * STAGE_BYTES;
        const uint32_t pAl = pAh + 10240, pBh = pAh + 20480, pBl = pAh + 30720;
        #pragma unroll
        for (int ks = 0; ks < 2; ++ks) {
            uint32_t ah[2][4], al[2][4];
            #pragma unroll
            for (int mt = 0; mt < 2; ++mt) {
                uint32_t ad = (uint32_t)(wm * 32 + mt * 16 + arow_off) * 80
                            + (uint32_t)(ks * 16 + acol_off) * 2;
                ldsm4(ah[mt], pAh + ad);
                ldsm4(al[mt], pAl + ad);
            }
            #pragma unroll
            for (int np = 0; np < 2; ++np) {
                uint32_t bd = (uint32_t)(wn * 32 + np * 16 + brow_off) * 80
                            + (uint32_t)(ks * 16 + bcol_off) * 2;
                uint32_t bh[4], bl[4];
                ldsm4(bh, pBh + bd);
                ldsm4(bl, pBl + bd);
                #pragma unroll
                for (int mt = 0; mt < 2; ++mt)
                    #pragma unroll
                    for (int nj = 0; nj < 2; ++nj) {
                        float* d = acc[mt][np * 2 + nj];
                        mma16816(d, ah[mt], bh + nj * 2);
                        mma16816(d, ah[mt], bl + nj * 2);
                        mma16816(d, al[mt], bh + nj * 2);
                    }
            }
        }
        __syncthreads();
    }

    // ---- epilogue through smem (stride 132 floats) ----
    float* smf = (float*)dsm;
    const int base_r = wm * 32 + (lane >> 2);
    const int base_c = wn * 32 + (lane & 3) * 2;
    #pragma unroll
    for (int mt = 0; mt < 2; ++mt)
        #pragma unroll
        for (int nt = 0; nt < 4; ++nt) {
            int r = base_r + mt * 16, c = base_c + (nt >> 1) * 16 + (nt & 1) * 8;
            if (mode == 0) {
                smf[r * 132 + c]           = acc[mt][nt][0];
                smf[r * 132 + c + 1]       = acc[mt][nt][1];
                smf[(r + 8) * 132 + c]     = acc[mt][nt][2];
                smf[(r + 8) * 132 + c + 1] = acc[mt][nt][3];
            } else {
                smf[c * 132 + r]           = acc[mt][nt][0];
                smf[(c + 1) * 132 + r]     = acc[mt][nt][1];
                smf[c * 132 + r + 8]       = acc[mt][nt][2];
                smf[(c + 1) * 132 + r + 8] = acc[mt][nt][3];
            }
        }
    __syncthreads();

    const float BNS = 0.99999500003749968f;
    if (mode == 0) {
        int o = t >> 2, nch = (t & 3) * 32;
        float sc = __ldg(gamma + o0 + o) * BNS;
        float bb = sc * __ldg(bias + o0 + o) + __ldg(beta + o0 + o);
        float* dst = Yf + ((size_t)b * O + o0 + o) * N + n0 + nch;
        #pragma unroll
        for (int j = 0; j < 32; j += 4) {
            float4 v;
            v.x = fmaxf(sc * smf[o * 132 + nch + j]     + bb, 0.f);
            v.y = fmaxf(sc * smf[o * 132 + nch + j + 1] + bb, 0.f);
            v.z = fmaxf(sc * smf[o * 132 + nch + j + 2] + bb, 0.f);
            v.w = fmaxf(sc * smf[o * 132 + nch + j + 3] + bb, 0.f);
            *(float4*)(dst + j) = v;
        }
    } else if (mode == 2) {
        int n = t >> 2, och = (t & 3) * 32;
        float* dst = Yf + ((size_t)b * N + n0 + n) * O + o0 + och;
        #pragma unroll
        for (int j = 0; j < 32; j += 4) {
            float4 v;
            v.x = smf[n * 132 + och + j];
            v.y = smf[n * 132 + och + j + 1];
            v.z = smf[n * 132 + och + j + 2];
            v.w = smf[n * 132 + och + j + 3];
            *(float4*)(dst + j) = v;
        }
    } else {
        int n = t >> 2, och = (t & 3) * 32;
        size_t off = ((size_t)b * N + n0 + n) * O + o0 + och;
        #pragma unroll
        for (int j0 = 0; j0 < 32; j0 += 8) {
            union { __nv_bfloat16 h[8]; uint4 u; } Hh, Ll;
            #pragma unroll
            for (int j = 0; j < 8; ++j) {
                int o = o0 + och + j0 + j;
                float sc = __ldg(gamma + o) * BNS;
                float bb = sc * __ldg(bias + o) + __ldg(beta + o);
                float v = fmaxf(sc * smf[n * 132 + och + j0 + j] + bb, 0.f);
                Hh.h[j] = __float2bfloat16(v);
                Ll.h[j] = __float2bfloat16(v - __bfloat162float(Hh.h[j]));
            }
            *(uint4*)(Yh + off + j0) = Hh.u;
            *(uint4*)(Yl + off + j0) = Ll.u;
        }
    }
}

// ---------------------------------------------------------------------------
extern "C" void kernel_launch(void* const* d_in, const int* in_sizes, int n_in,
                              void* d_out, int out_size)
{
    const float* radar = (const float*)d_in[0];
    const float* l1f   = (const float*)d_in[1];
    const float* l2f   = (const float*)d_in[2];
    const float* l0_l1 = (const float*)d_in[3];
    const float* l1_l2 = (const float*)d_in[4];
    const float* w21a  = (const float*)d_in[5];
    const float* b21a  = (const float*)d_in[6];
    const float* g21a  = (const float*)d_in[7];
    const float* be21a = (const float*)d_in[8];
    const float* w21b  = (const float*)d_in[9];
    const float* b21b  = (const float*)d_in[10];
    const float* g21b  = (const float*)d_in[11];
    const float* be21b = (const float*)d_in[12];
    const float* w10a  = (const float*)d_in[13];
    const float* b10a  = (const float*)d_in[14];
    const float* g10a  = (const float*)d_in[15];
    const float* be10a = (const float*)d_in[16];
    const float* w10b  = (const float*)d_in[17];
    const float* b10b  = (const float*)d_in[18];
    const float* g10b  = (const float*)d_in[19];
    const float* be10b = (const float*)d_in[20];

    cudaFuncSetAttribute(gemm_mma, cudaFuncAttributeMaxDynamicSharedMemorySize, GEMM_SMEM);

    __nv_bfloat16 *l1h,*l1l,*l2h,*l2l,*rdh,*rdl;
    __nv_bfloat16 *w21ah,*w21al,*w21bh,*w21bl,*w10ah,*w10al,*w10bh,*w10bl;
    __nv_bfloat16 *Y1h,*Y1l,*Fh,*Fl,*Y3h,*Y3l;
    float *G2,*H1,*G,*Hr,*w1,*w0;
    int *i1,*i0;
    cudaGetSymbolAddress((void**)&l1h, g_l1h);   cudaGetSymbolAddress((void**)&l1l, g_l1l);
    cudaGetSymbolAddress((void**)&l2h, g_l2h);   cudaGetSymbolAddress((void**)&l2l, g_l2l);
    cudaGetSymbolAddress((void**)&rdh, g_rdh);   cudaGetSymbolAddress((void**)&rdl, g_rdl);
    cudaGetSymbolAddress((void**)&w21ah, g_w21ah); cudaGetSymbolAddress((void**)&w21al, g_w21al);
    cudaGetSymbolAddress((void**)&w21bh, g_w21bh); cudaGetSymbolAddress((void**)&w21bl, g_w21bl);
    cudaGetSymbolAddress((void**)&w10ah, g_w10ah); cudaGetSymbolAddress((void**)&w10al, g_w10al);
    cudaGetSymbolAddress((void**)&w10bh, g_w10bh); cudaGetSymbolAddress((void**)&w10bl, g_w10bl);
    cudaGetSymbolAddress((void**)&Y1h, g_Y1h);   cudaGetSymbolAddress((void**)&Y1l, g_Y1l);
    cudaGetSymbolAddress((void**)&Fh,  g_Fh);    cudaGetSymbolAddress((void**)&Fl,  g_Fl);
    cudaGetSymbolAddress((void**)&Y3h, g_Y3h);   cudaGetSymbolAddress((void**)&Y3l, g_Y3l);
    cudaGetSymbolAddress((void**)&G2, g_G2);     cudaGetSymbolAddress((void**)&H1, g_H1);
    cudaGetSymbolAddress((void**)&G,  g_G);      cudaGetSymbolAddress((void**)&Hr, g_Hr);
    cudaGetSymbolAddress((void**)&i1, g_i1);     cudaGetSymbolAddress((void**)&w1, g_w1);
    cudaGetSymbolAddress((void**)&i0, g_i0);     cudaGetSymbolAddress((void**)&w0, g_w0);

    // KNN selections
    knn_topk<<<dim3(N1_/64, B_), 256>>>(l1_l2, N2_, N1_, i1, w1);
    knn_topk<<<dim3(N0_/64, B_), 256>>>(l0_l1, N1_, N0_, i0, w0);

    // hi/lo splits of raw inputs + weights
    cvt_hilo<<<(B_*N1_*128/4 + 255)/256, 256>>>(l1f,   l1h, l1l, B_*N1_*128/4);
    cvt_hilo<<<(B_*N2_*192/4 + 255)/256, 256>>>(l2f,   l2h, l2l, B_*N2_*192/4);
    cvt_hilo<<<(B_*N0_*64/4  + 255)/256, 256>>>(radar, rdh, rdl, B_*N0_*64/4);
    cvt_hilo<<<(640*320/4 + 255)/256, 256>>>(w21a, w21ah, w21al, 640*320/4);
    cvt_hilo<<<(640*640/4 + 255)/256, 256>>>(w21b, w21bh, w21bl, 640*640/4);
    cvt_hilo<<<(640*704/4 + 255)/256, 256>>>(w10a, w10ah, w10al, 640*704/4);
    cvt_hilo<<<(768*640/4 + 255)/256, 256>>>(w10b, w10bh, w10bl, 768*640/4);

    // level 2->1:  G2 = W21a[:,128:320]*l2f ; H1 = W21a[:,0:128]*l1f
    gemm_mma<<<dim3(N2_/128, 5, B_), 512, GEMM_SMEM>>>(w21ah+128, w21al+128, 320, l2h, l2l,
        G2, nullptr, nullptr, nullptr, nullptr, nullptr, 192, N2_, 640, 2);
    gemm_mma<<<dim3(N1_/128, 5, B_), 512, GEMM_SMEM>>>(w21ah, w21al, 320, l1h, l1l,
        H1, nullptr, nullptr, nullptr, nullptr, nullptr, 128, N1_, 640, 2);
    combine_bn_relu<<<dim3(N1_/8, B_), 256>>>(H1, G2, i1, w1, b21a, g21a, be21a, Y1h, Y1l, N1_, N2_);
    // layer 21b -> F (hi/lo)
    gemm_mma<<<dim3(N1_/128, 5, B_), 512, GEMM_SMEM>>>(w21bh, w21bl, 640, Y1h, Y1l,
        nullptr, Fh, Fl, b21b, g21b, be21b, 640, N1_, 640, 1);
    // level 1->0:  G = W10a[:,64:704]*F ; Hr = W10a[:,0:64]*radar
    gemm_mma<<<dim3(N1_/128, 5, B_), 512, GEMM_SMEM>>>(w10ah+64, w10al+64, 704, Fh, Fl,
        G, nullptr, nullptr, nullptr, nullptr, nullptr, 640, N1_, 640, 2);
    gemm_mma<<<dim3(N0_/128, 5, B_), 512, GEMM_SMEM>>>(w10ah, w10al, 704, rdh, rdl,
        Hr, nullptr, nullptr, nullptr, nullptr, nullptr, 64, N0_, 640, 2);
    combine_bn_relu<<<dim3(N0_/8, B_), 256>>>(Hr, G, i0, w0, b10a, g10a, be10a, Y3h, Y3l, N0_, N1_);
    // layer 10b -> channel-major d_out
    gemm_mma<<<dim3(N0_/128, 6, B_), 512, GEMM_SMEM>>>(w10bh, w10bl, 640, Y3h, Y3l,
        (float*)d_out, nullptr, nullptr, b10b, g10b, be10b, 640, N0_, 768, 0);
}

// round 8
// speedup vs baseline: 2.3605x; 1.0045x over previous
#include <cuda_runtime.h>
#include <cuda_bf16.h>
#include <cstdint>
#include <cstddef>

// ---------------------------------------------------------------------------
// FeaturePropogate via mma.sync bf16 (plain sm_103 PTX):
//   - interp pushed through first MLP layer (W*concat == W_a*feat + interp(W_b*F))
//   - GEMMs: 3-term error-compensated bf16 mma.sync (AhBh + AhBl + AlBh), fp32 acc
//   - dual accumulators (main/corr) for independent HMMA chains
//   - 3-stage cp.async pipeline, ONE __syncthreads per K-chunk
// ---------------------------------------------------------------------------

#define B_     4
#define N0_    8192
#define N1_    2048
#define N2_    512

// ---- device scratch (no allocation allowed) ----
__device__ __nv_bfloat16 g_l1h[(size_t)B_*N1_*128], g_l1l[(size_t)B_*N1_*128];
__device__ __nv_bfloat16 g_l2h[(size_t)B_*N2_*192], g_l2l[(size_t)B_*N2_*192];
__device__ __nv_bfloat16 g_rdh[(size_t)B_*N0_*64],  g_rdl[(size_t)B_*N0_*64];
__device__ __nv_bfloat16 g_w21ah[640*320], g_w21al[640*320];
__device__ __nv_bfloat16 g_w21bh[640*640], g_w21bl[640*640];
__device__ __nv_bfloat16 g_w10ah[640*704], g_w10al[640*704];
__device__ __nv_bfloat16 g_w10bh[768*640], g_w10bl[768*640];
__device__ __nv_bfloat16 g_Y1h[(size_t)B_*N1_*640], g_Y1l[(size_t)B_*N1_*640];
__device__ __nv_bfloat16 g_Fh [(size_t)B_*N1_*640], g_Fl [(size_t)B_*N1_*640];
__device__ __nv_bfloat16 g_Y3h[(size_t)B_*N0_*640], g_Y3l[(size_t)B_*N0_*640];
__device__ float g_G2[(size_t)B_*N2_*640];
__device__ float g_H1[(size_t)B_*N1_*640];
__device__ float g_G [(size_t)B_*N1_*640];
__device__ float g_Hr[(size_t)B_*N0_*640];
__device__ int   g_i1[(size_t)B_*N1_*8];
__device__ float g_w1[(size_t)B_*N1_*8];
__device__ int   g_i0[(size_t)B_*N0_*8];
__device__ float g_w0[(size_t)B_*N0_*8];

__device__ __forceinline__ uint32_t smem_u32_of(const void* p) {
    uint32_t a;
    asm("{ .reg .u64 t; cvta.to.shared.u64 t, %1; cvt.u32.u64 %0, t; }" : "=r"(a) : "l"(p));
    return a;
}
__device__ __forceinline__ void ldsm4(uint32_t* r, uint32_t addr) {
    asm volatile("ldmatrix.sync.aligned.m8n8.x4.shared.b16 {%0,%1,%2,%3}, [%4];"
                 : "=r"(r[0]), "=r"(r[1]), "=r"(r[2]), "=r"(r[3]) : "r"(addr));
}
__device__ __forceinline__ void mma16816(float* d, const uint32_t* a, const uint32_t* b) {
    asm volatile(
        "mma.sync.aligned.m16n8k16.row.col.f32.bf16.bf16.f32 "
        "{%0,%1,%2,%3}, {%4,%5,%6,%7}, {%8,%9}, {%0,%1,%2,%3};"
        : "+f"(d[0]), "+f"(d[1]), "+f"(d[2]), "+f"(d[3])
        : "r"(a[0]), "r"(a[1]), "r"(a[2]), "r"(a[3]), "r"(b[0]), "r"(b[1]));
}
__device__ __forceinline__ void cp16(uint32_t saddr, const void* gaddr) {
    asm volatile("cp.async.cg.shared.global [%0], [%1], 16;" :: "r"(saddr), "l"(gaddr));
}

// ---------------------------------------------------------------------------
// KNN top-8 (verified R3). D: [B][M][Npts], point n reads column n.
// ---------------------------------------------------------------------------
__global__ __launch_bounds__(256)
void knn_topk(const float* __restrict__ D, int M, int Npts,
              int* __restrict__ out_i, float* __restrict__ out_w)
{
    __shared__ float sd[64][4][8];
    __shared__ int   si[64][4][8];
    const int b   = blockIdx.y;
    const int p   = threadIdx.x & 63;
    const int q   = threadIdx.x >> 6;
    const int n   = blockIdx.x * 64 + p;
    const int seg = M >> 2;

    float bd[8]; int bi[8];
    #pragma unroll
    for (int j = 0; j < 8; ++j) { bd[j] = 3.4e38f; bi[j] = 0; }
    const float* col = D + (size_t)b * M * Npts + n + (size_t)(q * seg) * Npts;
    #pragma unroll 8
    for (int m = 0; m < seg; ++m) {
        float v = __ldg(col + (size_t)m * Npts);
        if (v < bd[7]) {
            bd[7] = v; bi[7] = q * seg + m;
            #pragma unroll
            for (int r = 7; r >= 1; --r) {
                if (bd[r] < bd[r-1]) {
                    float td = bd[r]; bd[r] = bd[r-1]; bd[r-1] = td;
                    int   ti = bi[r]; bi[r] = bi[r-1]; bi[r-1] = ti;
                }
            }
        }
    }
    #pragma unroll
    for (int j = 0; j < 8; ++j) { sd[p][q][j] = bd[j]; si[p][q][j] = bi[j]; }
    __syncthreads();

    if (threadIdx.x < 64) {
        const int pp = threadIdx.x;
        int p0 = 0, p1 = 0, p2 = 0, p3 = 0;
        float d8[8]; int i8[8];
        #pragma unroll
        for (int k = 0; k < 8; ++k) {
            float v0 = sd[pp][0][p0], v1 = sd[pp][1][p1];
            float v2 = sd[pp][2][p2], v3 = sd[pp][3][p3];
            float m01 = v0; int q01 = 0; if (v1 < m01) { m01 = v1; q01 = 1; }
            float m23 = v2; int q23 = 2; if (v3 < m23) { m23 = v3; q23 = 3; }
            float mv = m01; int qq = q01; if (m23 < m01) { mv = m23; qq = q23; }
            d8[k] = mv;
            if      (qq == 0) i8[k] = si[pp][0][p0++];
            else if (qq == 1) i8[k] = si[pp][1][p1++];
            else if (qq == 2) i8[k] = si[pp][2][p2++];
            else              i8[k] = si[pp][3][p3++];
        }
        float w[8], s = 0.f;
        #pragma unroll
        for (int j = 0; j < 8; ++j) { w[j] = 1.f / (d8[j] + 1e-8f); s += w[j]; }
        float inv = 1.f / (s + 1e-8f);
        const int nn = blockIdx.x * 64 + pp;
        size_t base = ((size_t)b * Npts + nn) * 8;
        #pragma unroll
        for (int j = 0; j < 8; ++j) { out_i[base + j] = i8[j]; out_w[base + j] = w[j] * inv; }
    }
}

// ---------------------------------------------------------------------------
// convert fp32 -> bf16 hi/lo planes
// ---------------------------------------------------------------------------
__global__ __launch_bounds__(256)
void cvt_hilo(const float* __restrict__ x, __nv_bfloat16* __restrict__ hi,
              __nv_bfloat16* __restrict__ lo, int n4)
{
    int i = blockIdx.x * 256 + threadIdx.x;
    if (i >= n4) return;
    float4 v = ((const float4*)x)[i];
    __nv_bfloat16 h0 = __float2bfloat16(v.x), h1 = __float2bfloat16(v.y);
    __nv_bfloat16 h2 = __float2bfloat16(v.z), h3 = __float2bfloat16(v.w);
    __nv_bfloat16 l0 = __float2bfloat16(v.x - __bfloat162float(h0));
    __nv_bfloat16 l1 = __float2bfloat16(v.y - __bfloat162float(h1));
    __nv_bfloat16 l2 = __float2bfloat16(v.z - __bfloat162float(h2));
    __nv_bfloat16 l3 = __float2bfloat16(v.w - __bfloat162float(h3));
    ((__nv_bfloat162*)hi)[i*2+0] = __nv_bfloat162(h0, h1);
    ((__nv_bfloat162*)hi)[i*2+1] = __nv_bfloat162(h2, h3);
    ((__nv_bfloat162*)lo)[i*2+0] = __nv_bfloat162(l0, l1);
    ((__nv_bfloat162*)lo)[i*2+1] = __nv_bfloat162(l2, l3);
}

// ---------------------------------------------------------------------------
// combine: v = ReLU(sc*(H[n] + sum_j w_j G[idx_j]) + bb) -> bf16 hi/lo planes
// ---------------------------------------------------------------------------
__global__ __launch_bounds__(256)
void combine_bn_relu(const float* __restrict__ H,    // [B][Np][640]
                     const float* __restrict__ G,    // [B][Ng][640]
                     const int*   __restrict__ knn_i,
                     const float* __restrict__ knn_w,
                     const float* __restrict__ bias,
                     const float* __restrict__ gamma,
                     const float* __restrict__ beta,
                     __nv_bfloat16* __restrict__ Yh,
                     __nv_bfloat16* __restrict__ Yl, int Np, int Ng)
{
    __shared__ float s_sc[640], s_bb[640];
    const float BNS = 0.99999500003749968f;   // 1/sqrt(1+1e-5)
    for (int c = threadIdx.x; c < 640; c += 256) {
        float sc = __ldg(gamma + c) * BNS;
        s_sc[c] = sc;
        s_bb[c] = sc * __ldg(bias + c) + __ldg(beta + c);
    }
    __syncthreads();
    const int b    = blockIdx.y;
    const int warp = threadIdx.x >> 5, lane = threadIdx.x & 31;
    const int n    = blockIdx.x * 8 + warp;
    const size_t pbase = (size_t)b * Np + n;

    int idx[8]; float w8[8];
    const int*   ip = knn_i + pbase * 8;
    const float* wp = knn_w + pbase * 8;
    #pragma unroll
    for (int j = 0; j < 8; ++j) { idx[j] = __ldg(ip + j); w8[j] = __ldg(wp + j); }

    const float* h = H + pbase * 640;
    float acc[20];
    #pragma unroll
    for (int r = 0; r < 20; ++r) acc[r] = __ldg(h + lane + 32 * r);
    #pragma unroll
    for (int j = 0; j < 8; ++j) {
        const float* g = G + ((size_t)b * Ng + idx[j]) * 640;
        const float wj = w8[j];
        #pragma unroll
        for (int r = 0; r < 20; ++r) acc[r] += wj * __ldg(g + lane + 32 * r);
    }
    #pragma unroll
    for (int r = 0; r < 20; ++r) {
        int c = lane + 32 * r;
        float v = fmaxf(s_sc[c] * acc[r] + s_bb[c], 0.f);
        __nv_bfloat16 hh = __float2bfloat16(v);
        Yh[pbase * 640 + c] = hh;
        Yl[pbase * 640 + c] = __float2bfloat16(v - __bfloat162float(hh));
    }
}

// ---------------------------------------------------------------------------
// mma.sync GEMM:  D[o][n] = sum_k W[o][k] * X[n][k]  (K-major bf16 hi/lo)
// 3-term compensation with DUAL accumulators, fp32. Block 128x128, K-chunk 32,
// 512 threads = 4x4 warps, warp tile 32x32. 3-stage cp.async pipeline,
// ONE __syncthreads per chunk. Padded smem stride 40 bf16 (LDSM conflict-free).
// mode: 0 = channel-major fp32 + BN+ReLU
//       1 = point-major bf16 hi/lo + BN+ReLU
//       2 = point-major fp32 raw
// ---------------------------------------------------------------------------
#define STAGE_BYTES 40960              // 4 planes x 128 x 40 bf16
#define GEMM_SMEM   (3 * STAGE_BYTES)  // 122880; epilogue (67584 B) reuses it

__global__ __launch_bounds__(512)
void gemm_mma(const __nv_bfloat16* __restrict__ Wh, const __nv_bfloat16* __restrict__ Wl, int ldW,
              const __nv_bfloat16* __restrict__ Xh, const __nv_bfloat16* __restrict__ Xl,
              float* __restrict__ Yf,
              __nv_bfloat16* __restrict__ Yh, __nv_bfloat16* __restrict__ Yl,
              const float* __restrict__ bias, const float* __restrict__ gamma,
              const float* __restrict__ beta,
              int K, int N, int O, int mode)
{
    extern __shared__ char dsm[];
    const uint32_t sbase = smem_u32_of(dsm);
    const int t = threadIdx.x, lane = t & 31, w = t >> 5;
    const int wm = w >> 2, wn = w & 3;
    const int b  = blockIdx.z;
    const int n0 = blockIdx.x * 128;
    const int o0 = blockIdx.y * 128;

    const __nv_bfloat16* srcs[4];
    srcs[0] = Wh + (size_t)o0 * ldW;
    srcs[1] = Wl + (size_t)o0 * ldW;
    srcs[2] = Xh + ((size_t)b * N + n0) * K;
    srcs[3] = Xl + ((size_t)b * N + n0) * K;
    int lds[4] = { ldW, ldW, K, K };

    // dual accumulators: main (AhBh) + corr (AhBl + AlBh)
    float accm[2][4][4], accc[2][4][4];
    #pragma unroll
    for (int i = 0; i < 2; ++i)
        #pragma unroll
        for (int j = 0; j < 4; ++j)
            #pragma unroll
            for (int e = 0; e < 4; ++e) { accm[i][j][e] = 0.f; accc[i][j][e] = 0.f; }

    // stage loader: 4 planes x 128 rows x 32 cols bf16, padded stride 40.
    // 128 rows x 4 x 16B chunks = 512 cp16 per plane = ONE per thread per plane.
    const int ld_row = t >> 2;
    const int ld_c4  = t & 3;
    auto cp_stage = [&](int k0, int buf) {
        uint32_t sb = sbase + buf * STAGE_BYTES + ld_row * 80 + ld_c4 * 16;
        #pragma unroll
        for (int pl = 0; pl < 4; ++pl) {
            cp16(sb + pl * 10240,
                 srcs[pl] + (size_t)ld_row * lds[pl] + k0 + ld_c4 * 8);
        }
        asm volatile("cp.async.commit_group;" ::: "memory");
    };

    const int g = lane >> 3;
    const int arow_off = (g & 1) * 8 + (lane & 7);
    const int acol_off = (g >> 1) * 8;
    const int brow_off = (g >> 1) * 8 + (lane & 7);
    const int bcol_off = (g & 1) * 8;

    const int nc = K >> 5;
    cp_stage(0, 0);
    if (nc > 1) cp_stage(32, 1);

    int buf = 0;
    for (int it = 0; it < nc; ++it) {
        if (it + 1 < nc) asm volatile("cp.async.wait_group 1;" ::: "memory");
        else             asm volatile("cp.async.wait_group 0;" ::: "memory");
        __syncthreads();
        if (it + 2 < nc) {
            int nb = buf + 2; if (nb >= 3) nb -= 3;
            cp_stage((it + 2) << 5, nb);
        }

        const uint32_t pAh = sbase + buf * STAGE_BYTES;
        const uint32_t pAl = pAh + 10240, pBh = pAh + 20480, pBl = pAh + 30720;
        #pragma unroll
        for (int ks = 0; ks < 2; ++ks) {
            uint32_t ah[2][4], al[2][4];
            #pragma unroll
            for (int mt = 0; mt < 2; ++mt) {
                uint32_t ad = (uint32_t)(wm * 32 + mt * 16 + arow_off) * 80
                            + (uint32_t)(ks * 16 + acol_off) * 2;
                ldsm4(ah[mt], pAh + ad);
                ldsm4(al[mt], pAl + ad);
            }
            #pragma unroll
            for (int np = 0; np < 2; ++np) {
                uint32_t bd = (uint32_t)(wn * 32 + np * 16 + brow_off) * 80
                            + (uint32_t)(ks * 16 + bcol_off) * 2;
                uint32_t bh[4], bl[4];
                ldsm4(bh, pBh + bd);
                ldsm4(bl, pBl + bd);
                #pragma unroll
                for (int mt = 0; mt < 2; ++mt)
                    #pragma unroll
                    for (int nj = 0; nj < 2; ++nj) {
                        mma16816(accm[mt][np * 2 + nj], ah[mt], bh + nj * 2);
                        mma16816(accc[mt][np * 2 + nj], ah[mt], bl + nj * 2);
                        mma16816(accc[mt][np * 2 + nj], al[mt], bh + nj * 2);
                    }
            }
        }
        ++buf; if (buf == 3) buf = 0;
    }
    __syncthreads();   // all MMA reads done before smem is reused by epilogue

    // ---- epilogue through smem (stride 132 floats) ----
    float* smf = (float*)dsm;
    const int base_r = wm * 32 + (lane >> 2);
    const int base_c = wn * 32 + (lane & 3) * 2;
    #pragma unroll
    for (int mt = 0; mt < 2; ++mt)
        #pragma unroll
        for (int nt = 0; nt < 4; ++nt) {
            float v0 = accm[mt][nt][0] + accc[mt][nt][0];
            float v1 = accm[mt][nt][1] + accc[mt][nt][1];
            float v2 = accm[mt][nt][2] + accc[mt][nt][2];
            float v3 = accm[mt][nt][3] + accc[mt][nt][3];
            int r = base_r + mt * 16, c = base_c + (nt >> 1) * 16 + (nt & 1) * 8;
            if (mode == 0) {
                smf[r * 132 + c]           = v0;
                smf[r * 132 + c + 1]       = v1;
                smf[(r + 8) * 132 + c]     = v2;
                smf[(r + 8) * 132 + c + 1] = v3;
            } else {
                smf[c * 132 + r]           = v0;
                smf[(c + 1) * 132 + r]     = v1;
                smf[c * 132 + r + 8]       = v2;
                smf[(c + 1) * 132 + r + 8] = v3;
            }
        }
    __syncthreads();

    const float BNS = 0.99999500003749968f;
    if (mode == 0) {
        int o = t >> 2, nch = (t & 3) * 32;
        float sc = __ldg(gamma + o0 + o) * BNS;
        float bb = sc * __ldg(bias + o0 + o) + __ldg(beta + o0 + o);
        float* dst = Yf + ((size_t)b * O + o0 + o) * N + n0 + nch;
        #pragma unroll
        for (int j = 0; j < 32; j += 4) {
            float4 v;
            v.x = fmaxf(sc * smf[o * 132 + nch + j]     + bb, 0.f);
            v.y = fmaxf(sc * smf[o * 132 + nch + j + 1] + bb, 0.f);
            v.z = fmaxf(sc * smf[o * 132 + nch + j + 2] + bb, 0.f);
            v.w = fmaxf(sc * smf[o * 132 + nch + j + 3] + bb, 0.f);
            *(float4*)(dst + j) = v;
        }
    } else if (mode == 2) {
        int n = t >> 2, och = (t & 3) * 32;
        float* dst = Yf + ((size_t)b * N + n0 + n) * O + o0 + och;
        #pragma unroll
        for (int j = 0; j < 32; j += 4) {
            float4 v;
            v.x = smf[n * 132 + och + j];
            v.y = smf[n * 132 + och + j + 1];
            v.z = smf[n * 132 + och + j + 2];
            v.w = smf[n * 132 + och + j + 3];
            *(float4*)(dst + j) = v;
        }
    } else {
        int n = t >> 2, och = (t & 3) * 32;
        size_t off = ((size_t)b * N + n0 + n) * O + o0 + och;
        #pragma unroll
        for (int j0 = 0; j0 < 32; j0 += 8) {
            union { __nv_bfloat16 h[8]; uint4 u; } Hh, Ll;
            #pragma unroll
            for (int j = 0; j < 8; ++j) {
                int o = o0 + och + j0 + j;
                float sc = __ldg(gamma + o) * BNS;
                float bb = sc * __ldg(bias + o) + __ldg(beta + o);
                float v = fmaxf(sc * smf[n * 132 + och + j0 + j] + bb, 0.f);
                Hh.h[j] = __float2bfloat16(v);
                Ll.h[j] = __float2bfloat16(v - __bfloat162float(Hh.h[j]));
            }
            *(uint4*)(Yh + off + j0) = Hh.u;
            *(uint4*)(Yl + off + j0) = Ll.u;
        }
    }
}

// ---------------------------------------------------------------------------
extern "C" void kernel_launch(void* const* d_in, const int* in_sizes, int n_in,
                              void* d_out, int out_size)
{
    const float* radar = (const float*)d_in[0];
    const float* l1f   = (const float*)d_in[1];
    const float* l2f   = (const float*)d_in[2];
    const float* l0_l1 = (const float*)d_in[3];
    const float* l1_l2 = (const float*)d_in[4];
    const float* w21a  = (const float*)d_in[5];
    const float* b21a  = (const float*)d_in[6];
    const float* g21a  = (const float*)d_in[7];
    const float* be21a = (const float*)d_in[8];
    const float* w21b  = (const float*)d_in[9];
    const float* b21b  = (const float*)d_in[10];
    const float* g21b  = (const float*)d_in[11];
    const float* be21b = (const float*)d_in[12];
    const float* w10a  = (const float*)d_in[13];
    const float* b10a  = (const float*)d_in[14];
    const float* g10a  = (const float*)d_in[15];
    const float* be10a = (const float*)d_in[16];
    const float* w10b  = (const float*)d_in[17];
    const float* b10b  = (const float*)d_in[18];
    const float* g10b  = (const float*)d_in[19];
    const float* be10b = (const float*)d_in[20];

    cudaFuncSetAttribute(gemm_mma, cudaFuncAttributeMaxDynamicSharedMemorySize, GEMM_SMEM);

    __nv_bfloat16 *l1h,*l1l,*l2h,*l2l,*rdh,*rdl;
    __nv_bfloat16 *w21ah,*w21al,*w21bh,*w21bl,*w10ah,*w10al,*w10bh,*w10bl;
    __nv_bfloat16 *Y1h,*Y1l,*Fh,*Fl,*Y3h,*Y3l;
    float *G2,*H1,*G,*Hr,*w1,*w0;
    int *i1,*i0;
    cudaGetSymbolAddress((void**)&l1h, g_l1h);   cudaGetSymbolAddress((void**)&l1l, g_l1l);
    cudaGetSymbolAddress((void**)&l2h, g_l2h);   cudaGetSymbolAddress((void**)&l2l, g_l2l);
    cudaGetSymbolAddress((void**)&rdh, g_rdh);   cudaGetSymbolAddress((void**)&rdl, g_rdl);
    cudaGetSymbolAddress((void**)&w21ah, g_w21ah); cudaGetSymbolAddress((void**)&w21al, g_w21al);
    cudaGetSymbolAddress((void**)&w21bh, g_w21bh); cudaGetSymbolAddress((void**)&w21bl, g_w21bl);
    cudaGetSymbolAddress((void**)&w10ah, g_w10ah); cudaGetSymbolAddress((void**)&w10al, g_w10al);
    cudaGetSymbolAddress((void**)&w10bh, g_w10bh); cudaGetSymbolAddress((void**)&w10bl, g_w10bl);
    cudaGetSymbolAddress((void**)&Y1h, g_Y1h);   cudaGetSymbolAddress((void**)&Y1l, g_Y1l);
    cudaGetSymbolAddress((void**)&Fh,  g_Fh);    cudaGetSymbolAddress((void**)&Fl,  g_Fl);
    cudaGetSymbolAddress((void**)&Y3h, g_Y3h);   cudaGetSymbolAddress((void**)&Y3l, g_Y3l);
    cudaGetSymbolAddress((void**)&G2, g_G2);     cudaGetSymbolAddress((void**)&H1, g_H1);
    cudaGetSymbolAddress((void**)&G,  g_G);      cudaGetSymbolAddress((void**)&Hr, g_Hr);
    cudaGetSymbolAddress((void**)&i1, g_i1);     cudaGetSymbolAddress((void**)&w1, g_w1);
    cudaGetSymbolAddress((void**)&i0, g_i0);     cudaGetSymbolAddress((void**)&w0, g_w0);

    // KNN selections
    knn_topk<<<dim3(N1_/64, B_), 256>>>(l1_l2, N2_, N1_, i1, w1);
    knn_topk<<<dim3(N0_/64, B_), 256>>>(l0_l1, N1_, N0_, i0, w0);

    // hi/lo splits of raw inputs + weights
    cvt_hilo<<<(B_*N1_*128/4 + 255)/256, 256>>>(l1f,   l1h, l1l, B_*N1_*128/4);
    cvt_hilo<<<(B_*N2_*192/4 + 255)/256, 256>>>(l2f,   l2h, l2l, B_*N2_*192/4);
    cvt_hilo<<<(B_*N0_*64/4  + 255)/256, 256>>>(radar, rdh, rdl, B_*N0_*64/4);
    cvt_hilo<<<(640*320/4 + 255)/256, 256>>>(w21a, w21ah, w21al, 640*320/4);
    cvt_hilo<<<(640*640/4 + 255)/256, 256>>>(w21b, w21bh, w21bl, 640*640/4);
    cvt_hilo<<<(640*704/4 + 255)/256, 256>>>(w10a, w10ah, w10al, 640*704/4);
    cvt_hilo<<<(768*640/4 + 255)/256, 256>>>(w10b, w10bh, w10bl, 768*640/4);

    // level 2->1:  G2 = W21a[:,128:320]*l2f ; H1 = W21a[:,0:128]*l1f
    gemm_mma<<<dim3(N2_/128, 5, B_), 512, GEMM_SMEM>>>(w21ah+128, w21al+128, 320, l2h, l2l,
        G2, nullptr, nullptr, nullptr, nullptr, nullptr, 192, N2_, 640, 2);
    gemm_mma<<<dim3(N1_/128, 5, B_), 512, GEMM_SMEM>>>(w21ah, w21al, 320, l1h, l1l,
        H1, nullptr, nullptr, nullptr, nullptr, nullptr, 128, N1_, 640, 2);
    combine_bn_relu<<<dim3(N1_/8, B_), 256>>>(H1, G2, i1, w1, b21a, g21a, be21a, Y1h, Y1l, N1_, N2_);
    // layer 21b -> F (hi/lo)
    gemm_mma<<<dim3(N1_/128, 5, B_), 512, GEMM_SMEM>>>(w21bh, w21bl, 640, Y1h, Y1l,
        nullptr, Fh, Fl, b21b, g21b, be21b, 640, N1_, 640, 1);
    // level 1->0:  G = W10a[:,64:704]*F ; Hr = W10a[:,0:64]*radar
    gemm_mma<<<dim3(N1_/128, 5, B_), 512, GEMM_SMEM>>>(w10ah+64, w10al+64, 704, Fh, Fl,
        G, nullptr, nullptr, nullptr, nullptr, nullptr, 640, N1_, 640, 2);
    gemm_mma<<<dim3(N0_/128, 5, B_), 512, GEMM_SMEM>>>(w10ah, w10al, 704, rdh, rdl,
        Hr, nullptr, nullptr, nullptr, nullptr, nullptr, 64, N0_, 640, 2);
    combine_bn_relu<<<dim3(N0_/8, B_), 256>>>(Hr, G, i0, w0, b10a, g10a, be10a, Y3h, Y3l, N0_, N1_);
    // layer 10b -> channel-major d_out
    gemm_mma<<<dim3(N0_/128, 6, B_), 512, GEMM_SMEM>>>(w10bh, w10bl, 640, Y3h, Y3l,
        (float*)d_out, nullptr, nullptr, b10b, g10b, be10b, 640, N0_, 768, 0);
}

// round 9
// speedup vs baseline: 2.6936x; 1.1411x over previous
#include <cuda_runtime.h>
#include <cuda_fp16.h>
#include <cstdint>
#include <cstddef>

// ---------------------------------------------------------------------------
// FeaturePropogate via mma.sync fp16 (plain sm_103 PTX):
//   - interp pushed through first MLP layer (W*concat == W_a*feat + interp(W_b*F))
//   - GEMMs: 2-term compensated fp16 mma.sync (Wh*X + Wl*X), fp32 accum
//     (weights split hi/lo; activations single fp16 — error ~2^-12/GEMM)
//   - 3-stage cp.async pipeline, one __syncthreads per K-chunk
// ---------------------------------------------------------------------------

#define B_     4
#define N0_    8192
#define N1_    2048
#define N2_    512

// ---- device scratch (no allocation allowed) ----
__device__ __half g_l1h[(size_t)B_*N1_*128];
__device__ __half g_l2h[(size_t)B_*N2_*192];
__device__ __half g_rdh[(size_t)B_*N0_*64];
__device__ __half g_w21ah[640*320], g_w21al[640*320];
__device__ __half g_w21bh[640*640], g_w21bl[640*640];
__device__ __half g_w10ah[640*704], g_w10al[640*704];
__device__ __half g_w10bh[768*640], g_w10bl[768*640];
__device__ __half g_Y1h[(size_t)B_*N1_*640];
__device__ __half g_Fh [(size_t)B_*N1_*640];
__device__ __half g_Y3h[(size_t)B_*N0_*640];
__device__ float g_G2[(size_t)B_*N2_*640];
__device__ float g_H1[(size_t)B_*N1_*640];
__device__ float g_G [(size_t)B_*N1_*640];
__device__ float g_Hr[(size_t)B_*N0_*640];
__device__ int   g_i1[(size_t)B_*N1_*8];
__device__ float g_w1[(size_t)B_*N1_*8];
__device__ int   g_i0[(size_t)B_*N0_*8];
__device__ float g_w0[(size_t)B_*N0_*8];

__device__ __forceinline__ uint32_t smem_u32_of(const void* p) {
    uint32_t a;
    asm("{ .reg .u64 t; cvta.to.shared.u64 t, %1; cvt.u32.u64 %0, t; }" : "=r"(a) : "l"(p));
    return a;
}
__device__ __forceinline__ void ldsm4(uint32_t* r, uint32_t addr) {
    asm volatile("ldmatrix.sync.aligned.m8n8.x4.shared.b16 {%0,%1,%2,%3}, [%4];"
                 : "=r"(r[0]), "=r"(r[1]), "=r"(r[2]), "=r"(r[3]) : "r"(addr));
}
__device__ __forceinline__ void mma16816(float* d, const uint32_t* a, const uint32_t* b) {
    asm volatile(
        "mma.sync.aligned.m16n8k16.row.col.f32.f16.f16.f32 "
        "{%0,%1,%2,%3}, {%4,%5,%6,%7}, {%8,%9}, {%0,%1,%2,%3};"
        : "+f"(d[0]), "+f"(d[1]), "+f"(d[2]), "+f"(d[3])
        : "r"(a[0]), "r"(a[1]), "r"(a[2]), "r"(a[3]), "r"(b[0]), "r"(b[1]));
}
__device__ __forceinline__ void cp16(uint32_t saddr, const void* gaddr) {
    asm volatile("cp.async.cg.shared.global [%0], [%1], 16;" :: "r"(saddr), "l"(gaddr));
}

// ---------------------------------------------------------------------------
// KNN top-8 (verified R3). D: [B][M][Npts], point n reads column n.
// ---------------------------------------------------------------------------
__global__ __launch_bounds__(256)
void knn_topk(const float* __restrict__ D, int M, int Npts,
              int* __restrict__ out_i, float* __restrict__ out_w)
{
    __shared__ float sd[64][4][8];
    __shared__ int   si[64][4][8];
    const int b   = blockIdx.y;
    const int p   = threadIdx.x & 63;
    const int q   = threadIdx.x >> 6;
    const int n   = blockIdx.x * 64 + p;
    const int seg = M >> 2;

    float bd[8]; int bi[8];
    #pragma unroll
    for (int j = 0; j < 8; ++j) { bd[j] = 3.4e38f; bi[j] = 0; }
    const float* col = D + (size_t)b * M * Npts + n + (size_t)(q * seg) * Npts;
    #pragma unroll 8
    for (int m = 0; m < seg; ++m) {
        float v = __ldg(col + (size_t)m * Npts);
        if (v < bd[7]) {
            bd[7] = v; bi[7] = q * seg + m;
            #pragma unroll
            for (int r = 7; r >= 1; --r) {
                if (bd[r] < bd[r-1]) {
                    float td = bd[r]; bd[r] = bd[r-1]; bd[r-1] = td;
                    int   ti = bi[r]; bi[r] = bi[r-1]; bi[r-1] = ti;
                }
            }
        }
    }
    #pragma unroll
    for (int j = 0; j < 8; ++j) { sd[p][q][j] = bd[j]; si[p][q][j] = bi[j]; }
    __syncthreads();

    if (threadIdx.x < 64) {
        const int pp = threadIdx.x;
        int p0 = 0, p1 = 0, p2 = 0, p3 = 0;
        float d8[8]; int i8[8];
        #pragma unroll
        for (int k = 0; k < 8; ++k) {
            float v0 = sd[pp][0][p0], v1 = sd[pp][1][p1];
            float v2 = sd[pp][2][p2], v3 = sd[pp][3][p3];
            float m01 = v0; int q01 = 0; if (v1 < m01) { m01 = v1; q01 = 1; }
            float m23 = v2; int q23 = 2; if (v3 < m23) { m23 = v3; q23 = 3; }
            float mv = m01; int qq = q01; if (m23 < m01) { mv = m23; qq = q23; }
            d8[k] = mv;
            if      (qq == 0) i8[k] = si[pp][0][p0++];
            else if (qq == 1) i8[k] = si[pp][1][p1++];
            else if (qq == 2) i8[k] = si[pp][2][p2++];
            else              i8[k] = si[pp][3][p3++];
        }
        float w[8], s = 0.f;
        #pragma unroll
        for (int j = 0; j < 8; ++j) { w[j] = 1.f / (d8[j] + 1e-8f); s += w[j]; }
        float inv = 1.f / (s + 1e-8f);
        const int nn = blockIdx.x * 64 + pp;
        size_t base = ((size_t)b * Npts + nn) * 8;
        #pragma unroll
        for (int j = 0; j < 8; ++j) { out_i[base + j] = i8[j]; out_w[base + j] = w[j] * inv; }
    }
}

// ---------------------------------------------------------------------------
// converts
// ---------------------------------------------------------------------------
__global__ __launch_bounds__(256)
void cvt_w_hilo(const float* __restrict__ x, __half* __restrict__ hi,
                __half* __restrict__ lo, int n4)
{
    int i = blockIdx.x * 256 + threadIdx.x;
    if (i >= n4) return;
    float4 v = ((const float4*)x)[i];
    __half h0 = __float2half_rn(v.x), h1 = __float2half_rn(v.y);
    __half h2 = __float2half_rn(v.z), h3 = __float2half_rn(v.w);
    __half l0 = __float2half_rn(v.x - __half2float(h0));
    __half l1 = __float2half_rn(v.y - __half2float(h1));
    __half l2 = __float2half_rn(v.z - __half2float(h2));
    __half l3 = __float2half_rn(v.w - __half2float(h3));
    ((__half2*)hi)[i*2+0] = __halves2half2(h0, h1);
    ((__half2*)hi)[i*2+1] = __halves2half2(h2, h3);
    ((__half2*)lo)[i*2+0] = __halves2half2(l0, l1);
    ((__half2*)lo)[i*2+1] = __halves2half2(l2, l3);
}

__global__ __launch_bounds__(256)
void cvt_x_half(const float* __restrict__ x, __half* __restrict__ hi, int n4)
{
    int i = blockIdx.x * 256 + threadIdx.x;
    if (i >= n4) return;
    float4 v = ((const float4*)x)[i];
    ((__half2*)hi)[i*2+0] = __halves2half2(__float2half_rn(v.x), __float2half_rn(v.y));
    ((__half2*)hi)[i*2+1] = __halves2half2(__float2half_rn(v.z), __float2half_rn(v.w));
}

// ---------------------------------------------------------------------------
// combine: v = ReLU(sc*(H[n] + sum_j w_j G[idx_j]) + bb) -> single fp16 plane
// ---------------------------------------------------------------------------
__global__ __launch_bounds__(256)
void combine_bn_relu(const float* __restrict__ H,    // [B][Np][640]
                     const float* __restrict__ G,    // [B][Ng][640]
                     const int*   __restrict__ knn_i,
                     const float* __restrict__ knn_w,
                     const float* __restrict__ bias,
                     const float* __restrict__ gamma,
                     const float* __restrict__ beta,
                     __half* __restrict__ Yh, int Np, int Ng)
{
    __shared__ float s_sc[640], s_bb[640];
    const float BNS = 0.99999500003749968f;   // 1/sqrt(1+1e-5)
    for (int c = threadIdx.x; c < 640; c += 256) {
        float sc = __ldg(gamma + c) * BNS;
        s_sc[c] = sc;
        s_bb[c] = sc * __ldg(bias + c) + __ldg(beta + c);
    }
    __syncthreads();
    const int b    = blockIdx.y;
    const int warp = threadIdx.x >> 5, lane = threadIdx.x & 31;
    const int n    = blockIdx.x * 8 + warp;
    const size_t pbase = (size_t)b * Np + n;

    int idx[8]; float w8[8];
    const int*   ip = knn_i + pbase * 8;
    const float* wp = knn_w + pbase * 8;
    #pragma unroll
    for (int j = 0; j < 8; ++j) { idx[j] = __ldg(ip + j); w8[j] = __ldg(wp + j); }

    const float* h = H + pbase * 640;
    float acc[20];
    #pragma unroll
    for (int r = 0; r < 20; ++r) acc[r] = __ldg(h + lane + 32 * r);
    #pragma unroll
    for (int j = 0; j < 8; ++j) {
        const float* g = G + ((size_t)b * Ng + idx[j]) * 640;
        const float wj = w8[j];
        #pragma unroll
        for (int r = 0; r < 20; ++r) acc[r] += wj * __ldg(g + lane + 32 * r);
    }
    #pragma unroll
    for (int r = 0; r < 20; ++r) {
        int c = lane + 32 * r;
        float v = fmaxf(s_sc[c] * acc[r] + s_bb[c], 0.f);
        Yh[pbase * 640 + c] = __float2half_rn(v);
    }
}

// ---------------------------------------------------------------------------
// mma.sync fp16 GEMM:  D[o][n] = sum_k W[o][k] * X[n][k]
// W split hi/lo (2-term compensation), X single fp16, fp32 accum.
// Block 128x128, K-chunk 32, 512 threads = 4x4 warps, warp tile 32x32.
// 3-stage cp.async pipeline (3 planes/stage), one __syncthreads per chunk.
// mode: 0 = channel-major fp32 + BN+ReLU
//       1 = point-major fp16 + BN+ReLU
//       2 = point-major fp32 raw
// ---------------------------------------------------------------------------
#define PLANE_BYTES 10240              // 128 rows x 40 halves (80 B padded)
#define STAGE_BYTES (3 * PLANE_BYTES)  // Wh, Wl, Xh
#define GEMM_SMEM   (3 * STAGE_BYTES)  // 92160; epilogue (67584 B) reuses it

__global__ __launch_bounds__(512)
void gemm_mma(const __half* __restrict__ Wh, const __half* __restrict__ Wl, int ldW,
              const __half* __restrict__ Xh,
              float* __restrict__ Yf, __half* __restrict__ Yhp,
              const float* __restrict__ bias, const float* __restrict__ gamma,
              const float* __restrict__ beta,
              int K, int N, int O, int mode)
{
    extern __shared__ char dsm[];
    const uint32_t sbase = smem_u32_of(dsm);
    const int t = threadIdx.x, lane = t & 31, w = t >> 5;
    const int wm = w >> 2, wn = w & 3;
    const int b  = blockIdx.z;
    const int n0 = blockIdx.x * 128;
    const int o0 = blockIdx.y * 128;

    const __half* srcs[3];
    srcs[0] = Wh + (size_t)o0 * ldW;
    srcs[1] = Wl + (size_t)o0 * ldW;
    srcs[2] = Xh + ((size_t)b * N + n0) * K;
    int lds[3] = { ldW, ldW, K };

    float accm[2][4][4], accc[2][4][4];
    #pragma unroll
    for (int i = 0; i < 2; ++i)
        #pragma unroll
        for (int j = 0; j < 4; ++j)
            #pragma unroll
            for (int e = 0; e < 4; ++e) { accm[i][j][e] = 0.f; accc[i][j][e] = 0.f; }

    // stage loader: 3 planes x 128 rows x 32 halves, padded stride 40 halves.
    // 128 rows x 4 x 16B chunks = 512 cp16 per plane = one per thread per plane.
    const int ld_row = t >> 2;
    const int ld_c4  = t & 3;
    auto cp_stage = [&](int k0, int buf) {
        uint32_t sb = sbase + buf * STAGE_BYTES + ld_row * 80 + ld_c4 * 16;
        #pragma unroll
        for (int pl = 0; pl < 3; ++pl) {
            cp16(sb + pl * PLANE_BYTES,
                 srcs[pl] + (size_t)ld_row * lds[pl] + k0 + ld_c4 * 8);
        }
        asm volatile("cp.async.commit_group;" ::: "memory");
    };

    const int g = lane >> 3;
    const int arow_off = (g & 1) * 8 + (lane & 7);
    const int acol_off = (g >> 1) * 8;
    const int brow_off = (g >> 1) * 8 + (lane & 7);
    const int bcol_off = (g & 1) * 8;

    const int nc = K >> 5;
    cp_stage(0, 0);
    if (nc > 1) cp_stage(32, 1);

    int buf = 0;
    for (int it = 0; it < nc; ++it) {
        if (it + 1 < nc) asm volatile("cp.async.wait_group 1;" ::: "memory");
        else             asm volatile("cp.async.wait_group 0;" ::: "memory");
        __syncthreads();
        if (it + 2 < nc) {
            int nb = buf + 2; if (nb >= 3) nb -= 3;
            cp_stage((it + 2) << 5, nb);
        }

        const uint32_t pAh = sbase + buf * STAGE_BYTES;
        const uint32_t pAl = pAh + PLANE_BYTES, pBh = pAh + 2 * PLANE_BYTES;
        #pragma unroll
        for (int ks = 0; ks < 2; ++ks) {
            uint32_t ah[2][4], al[2][4];
            #pragma unroll
            for (int mt = 0; mt < 2; ++mt) {
                uint32_t ad = (uint32_t)(wm * 32 + mt * 16 + arow_off) * 80
                            + (uint32_t)(ks * 16 + acol_off) * 2;
                ldsm4(ah[mt], pAh + ad);
                ldsm4(al[mt], pAl + ad);
            }
            #pragma unroll
            for (int np = 0; np < 2; ++np) {
                uint32_t bd = (uint32_t)(wn * 32 + np * 16 + brow_off) * 80
                            + (uint32_t)(ks * 16 + bcol_off) * 2;
                uint32_t bh[4];
                ldsm4(bh, pBh + bd);
                #pragma unroll
                for (int mt = 0; mt < 2; ++mt)
                    #pragma unroll
                    for (int nj = 0; nj < 2; ++nj) {
                        mma16816(accm[mt][np * 2 + nj], ah[mt], bh + nj * 2);
                        mma16816(accc[mt][np * 2 + nj], al[mt], bh + nj * 2);
                    }
            }
        }
        ++buf; if (buf == 3) buf = 0;
    }
    __syncthreads();   // all MMA reads done before smem reuse

    // ---- epilogue through smem (stride 132 floats) ----
    float* smf = (float*)dsm;
    const int base_r = wm * 32 + (lane >> 2);
    const int base_c = wn * 32 + (lane & 3) * 2;
    #pragma unroll
    for (int mt = 0; mt < 2; ++mt)
        #pragma unroll
        for (int nt = 0; nt < 4; ++nt) {
            float v0 = accm[mt][nt][0] + accc[mt][nt][0];
            float v1 = accm[mt][nt][1] + accc[mt][nt][1];
            float v2 = accm[mt][nt][2] + accc[mt][nt][2];
            float v3 = accm[mt][nt][3] + accc[mt][nt][3];
            int r = base_r + mt * 16, c = base_c + (nt >> 1) * 16 + (nt & 1) * 8;
            if (mode == 0) {
                smf[r * 132 + c]           = v0;
                smf[r * 132 + c + 1]       = v1;
                smf[(r + 8) * 132 + c]     = v2;
                smf[(r + 8) * 132 + c + 1] = v3;
            } else {
                smf[c * 132 + r]           = v0;
                smf[(c + 1) * 132 + r]     = v1;
                smf[c * 132 + r + 8]       = v2;
                smf[(c + 1) * 132 + r + 8] = v3;
            }
        }
    __syncthreads();

    const float BNS = 0.99999500003749968f;
    if (mode == 0) {
        int o = t >> 2, nch = (t & 3) * 32;
        float sc = __ldg(gamma + o0 + o) * BNS;
        float bb = sc * __ldg(bias + o0 + o) + __ldg(beta + o0 + o);
        float* dst = Yf + ((size_t)b * O + o0 + o) * N + n0 + nch;
        #pragma unroll
        for (int j = 0; j < 32; j += 4) {
            float4 v;
            v.x = fmaxf(sc * smf[o * 132 + nch + j]     + bb, 0.f);
            v.y = fmaxf(sc * smf[o * 132 + nch + j + 1] + bb, 0.f);
            v.z = fmaxf(sc * smf[o * 132 + nch + j + 2] + bb, 0.f);
            v.w = fmaxf(sc * smf[o * 132 + nch + j + 3] + bb, 0.f);
            *(float4*)(dst + j) = v;
        }
    } else if (mode == 2) {
        int n = t >> 2, och = (t & 3) * 32;
        float* dst = Yf + ((size_t)b * N + n0 + n) * O + o0 + och;
        #pragma unroll
        for (int j = 0; j < 32; j += 4) {
            float4 v;
            v.x = smf[n * 132 + och + j];
            v.y = smf[n * 132 + och + j + 1];
            v.z = smf[n * 132 + och + j + 2];
            v.w = smf[n * 132 + och + j + 3];
            *(float4*)(dst + j) = v;
        }
    } else {
        int n = t >> 2, och = (t & 3) * 32;
        size_t off = ((size_t)b * N + n0 + n) * O + o0 + och;
        #pragma unroll
        for (int j0 = 0; j0 < 32; j0 += 8) {
            union { __half h[8]; uint4 u; } Hh;
            #pragma unroll
            for (int j = 0; j < 8; ++j) {
                int o = o0 + och + j0 + j;
                float sc = __ldg(gamma + o) * BNS;
                float bb = sc * __ldg(bias + o) + __ldg(beta + o);
                float v = fmaxf(sc * smf[n * 132 + och + j0 + j] + bb, 0.f);
                Hh.h[j] = __float2half_rn(v);
            }
            *(uint4*)(Yhp + off + j0) = Hh.u;
        }
    }
}

// ---------------------------------------------------------------------------
extern "C" void kernel_launch(void* const* d_in, const int* in_sizes, int n_in,
                              void* d_out, int out_size)
{
    const float* radar = (const float*)d_in[0];
    const float* l1f   = (const float*)d_in[1];
    const float* l2f   = (const float*)d_in[2];
    const float* l0_l1 = (const float*)d_in[3];
    const float* l1_l2 = (const float*)d_in[4];
    const float* w21a  = (const float*)d_in[5];
    const float* b21a  = (const float*)d_in[6];
    const float* g21a  = (const float*)d_in[7];
    const float* be21a = (const float*)d_in[8];
    const float* w21b  = (const float*)d_in[9];
    const float* b21b  = (const float*)d_in[10];
    const float* g21b  = (const float*)d_in[11];
    const float* be21b = (const float*)d_in[12];
    const float* w10a  = (const float*)d_in[13];
    const float* b10a  = (const float*)d_in[14];
    const float* g10a  = (const float*)d_in[15];
    const float* be10a = (const float*)d_in[16];
    const float* w10b  = (const float*)d_in[17];
    const float* b10b  = (const float*)d_in[18];
    const float* g10b  = (const float*)d_in[19];
    const float* be10b = (const float*)d_in[20];

    cudaFuncSetAttribute(gemm_mma, cudaFuncAttributeMaxDynamicSharedMemorySize, GEMM_SMEM);

    __half *l1h,*l2h,*rdh;
    __half *w21ah,*w21al,*w21bh,*w21bl,*w10ah,*w10al,*w10bh,*w10bl;
    __half *Y1h,*Fh,*Y3h;
    float *G2,*H1,*G,*Hr,*w1,*w0;
    int *i1,*i0;
    cudaGetSymbolAddress((void**)&l1h, g_l1h);
    cudaGetSymbolAddress((void**)&l2h, g_l2h);
    cudaGetSymbolAddress((void**)&rdh, g_rdh);
    cudaGetSymbolAddress((void**)&w21ah, g_w21ah); cudaGetSymbolAddress((void**)&w21al, g_w21al);
    cudaGetSymbolAddress((void**)&w21bh, g_w21bh); cudaGetSymbolAddress((void**)&w21bl, g_w21bl);
    cudaGetSymbolAddress((void**)&w10ah, g_w10ah); cudaGetSymbolAddress((void**)&w10al, g_w10al);
    cudaGetSymbolAddress((void**)&w10bh, g_w10bh); cudaGetSymbolAddress((void**)&w10bl, g_w10bl);
    cudaGetSymbolAddress((void**)&Y1h, g_Y1h);
    cudaGetSymbolAddress((void**)&Fh,  g_Fh);
    cudaGetSymbolAddress((void**)&Y3h, g_Y3h);
    cudaGetSymbolAddress((void**)&G2, g_G2);     cudaGetSymbolAddress((void**)&H1, g_H1);
    cudaGetSymbolAddress((void**)&G,  g_G);      cudaGetSymbolAddress((void**)&Hr, g_Hr);
    cudaGetSymbolAddress((void**)&i1, g_i1);     cudaGetSymbolAddress((void**)&w1, g_w1);
    cudaGetSymbolAddress((void**)&i0, g_i0);     cudaGetSymbolAddress((void**)&w0, g_w0);

    // launches 1-5 (skipped by ncu -s 5): knn x2 + 3 converts
    knn_topk<<<dim3(N1_/64, B_), 256>>>(l1_l2, N2_, N1_, i1, w1);
    knn_topk<<<dim3(N0_/64, B_), 256>>>(l0_l1, N1_, N0_, i0, w0);
    cvt_x_half<<<(B_*N1_*128/4 + 255)/256, 256>>>(l1f, l1h, B_*N1_*128/4);
    cvt_x_half<<<(B_*N2_*192/4 + 255)/256, 256>>>(l2f, l2h, B_*N2_*192/4);
    cvt_w_hilo<<<(640*320/4 + 255)/256, 256>>>(w21a, w21ah, w21al, 640*320/4);

    // launch 6 (PROFILED): H1 = W21a[:,0:128]*l1f
    gemm_mma<<<dim3(N1_/128, 5, B_), 512, GEMM_SMEM>>>(w21ah, w21al, 320, l1h,
        H1, nullptr, nullptr, nullptr, nullptr, 128, N1_, 640, 2);
    // G2 = W21a[:,128:320]*l2f
    gemm_mma<<<dim3(N2_/128, 5, B_), 512, GEMM_SMEM>>>(w21ah+128, w21al+128, 320, l2h,
        G2, nullptr, nullptr, nullptr, nullptr, 192, N2_, 640, 2);
    combine_bn_relu<<<dim3(N1_/8, B_), 256>>>(H1, G2, i1, w1, b21a, g21a, be21a, Y1h, N1_, N2_);

    cvt_w_hilo<<<(640*640/4 + 255)/256, 256>>>(w21b, w21bh, w21bl, 640*640/4);
    gemm_mma<<<dim3(N1_/128, 5, B_), 512, GEMM_SMEM>>>(w21bh, w21bl, 640, Y1h,
        nullptr, Fh, b21b, g21b, be21b, 640, N1_, 640, 1);

    cvt_w_hilo<<<(640*704/4 + 255)/256, 256>>>(w10a, w10ah, w10al, 640*704/4);
    cvt_x_half<<<(B_*N0_*64/4 + 255)/256, 256>>>(radar, rdh, B_*N0_*64/4);
    gemm_mma<<<dim3(N1_/128, 5, B_), 512, GEMM_SMEM>>>(w10ah+64, w10al+64, 704, Fh,
        G, nullptr, nullptr, nullptr, nullptr, 640, N1_, 640, 2);
    gemm_mma<<<dim3(N0_/128, 5, B_), 512, GEMM_SMEM>>>(w10ah, w10al, 704, rdh,
        Hr, nullptr, nullptr, nullptr, nullptr, 64, N0_, 640, 2);
    combine_bn_relu<<<dim3(N0_/8, B_), 256>>>(Hr, G, i0, w0, b10a, g10a, be10a, Y3h, N0_, N1_);

    cvt_w_hilo<<<(768*640/4 + 255)/256, 256>>>(w10b, w10bh, w10bl, 768*640/4);
    gemm_mma<<<dim3(N0_/128, 6, B_), 512, GEMM_SMEM>>>(w10bh, w10bl, 640, Y3h,
        (float*)d_out, nullptr, b10b, g10b, be10b, 640, N0_, 768, 0);
}

// round 10
// speedup vs baseline: 3.3123x; 1.2297x over previous
#include <cuda_runtime.h>
#include <cuda_fp16.h>
#include <cstdint>
#include <cstddef>

// ---------------------------------------------------------------------------
// FeaturePropogate via mma.sync fp16 (plain sm_103 PTX):
//   - interp pushed through first MLP layer (W*concat == W_a*feat + interp(W_b*F))
//   - GEMMs: plain fp16 mma.sync, fp32 accum (validated error model: ~1.9e-4)
//   - K-chunk 64, 3-stage cp.async pipeline, one __syncthreads per chunk
// ---------------------------------------------------------------------------

#define B_     4
#define N0_    8192
#define N1_    2048
#define N2_    512

// ---- device scratch (no allocation allowed) ----
__device__ __half g_l1h[(size_t)B_*N1_*128];
__device__ __half g_l2h[(size_t)B_*N2_*192];
__device__ __half g_rdh[(size_t)B_*N0_*64];
__device__ __half g_w21ah[640*320];
__device__ __half g_w21bh[640*640];
__device__ __half g_w10ah[640*704];
__device__ __half g_w10bh[768*640];
__device__ __half g_Y1h[(size_t)B_*N1_*640];
__device__ __half g_Fh [(size_t)B_*N1_*640];
__device__ __half g_Y3h[(size_t)B_*N0_*640];
__device__ float g_G2[(size_t)B_*N2_*640];
__device__ float g_H1[(size_t)B_*N1_*640];
__device__ float g_G [(size_t)B_*N1_*640];
__device__ float g_Hr[(size_t)B_*N0_*640];
__device__ int   g_i1[(size_t)B_*N1_*8];
__device__ float g_w1[(size_t)B_*N1_*8];
__device__ int   g_i0[(size_t)B_*N0_*8];
__device__ float g_w0[(size_t)B_*N0_*8];

__device__ __forceinline__ uint32_t smem_u32_of(const void* p) {
    uint32_t a;
    asm("{ .reg .u64 t; cvta.to.shared.u64 t, %1; cvt.u32.u64 %0, t; }" : "=r"(a) : "l"(p));
    return a;
}
__device__ __forceinline__ void ldsm4(uint32_t* r, uint32_t addr) {
    asm volatile("ldmatrix.sync.aligned.m8n8.x4.shared.b16 {%0,%1,%2,%3}, [%4];"
                 : "=r"(r[0]), "=r"(r[1]), "=r"(r[2]), "=r"(r[3]) : "r"(addr));
}
__device__ __forceinline__ void mma16816(float* d, const uint32_t* a, const uint32_t* b) {
    asm volatile(
        "mma.sync.aligned.m16n8k16.row.col.f32.f16.f16.f32 "
        "{%0,%1,%2,%3}, {%4,%5,%6,%7}, {%8,%9}, {%0,%1,%2,%3};"
        : "+f"(d[0]), "+f"(d[1]), "+f"(d[2]), "+f"(d[3])
        : "r"(a[0]), "r"(a[1]), "r"(a[2]), "r"(a[3]), "r"(b[0]), "r"(b[1]));
}
__device__ __forceinline__ void cp16(uint32_t saddr, const void* gaddr) {
    asm volatile("cp.async.cg.shared.global [%0], [%1], 16;" :: "r"(saddr), "l"(gaddr));
}

// ---------------------------------------------------------------------------
// KNN top-8 (verified R3). D: [B][M][Npts], point n reads column n.
// ---------------------------------------------------------------------------
__global__ __launch_bounds__(256)
void knn_topk(const float* __restrict__ D, int M, int Npts,
              int* __restrict__ out_i, float* __restrict__ out_w)
{
    __shared__ float sd[64][4][8];
    __shared__ int   si[64][4][8];
    const int b   = blockIdx.y;
    const int p   = threadIdx.x & 63;
    const int q   = threadIdx.x >> 6;
    const int n   = blockIdx.x * 64 + p;
    const int seg = M >> 2;

    float bd[8]; int bi[8];
    #pragma unroll
    for (int j = 0; j < 8; ++j) { bd[j] = 3.4e38f; bi[j] = 0; }
    const float* col = D + (size_t)b * M * Npts + n + (size_t)(q * seg) * Npts;
    #pragma unroll 8
    for (int m = 0; m < seg; ++m) {
        float v = __ldg(col + (size_t)m * Npts);
        if (v < bd[7]) {
            bd[7] = v; bi[7] = q * seg + m;
            #pragma unroll
            for (int r = 7; r >= 1; --r) {
                if (bd[r] < bd[r-1]) {
                    float td = bd[r]; bd[r] = bd[r-1]; bd[r-1] = td;
                    int   ti = bi[r]; bi[r] = bi[r-1]; bi[r-1] = ti;
                }
            }
        }
    }
    #pragma unroll
    for (int j = 0; j < 8; ++j) { sd[p][q][j] = bd[j]; si[p][q][j] = bi[j]; }
    __syncthreads();

    if (threadIdx.x < 64) {
        const int pp = threadIdx.x;
        int p0 = 0, p1 = 0, p2 = 0, p3 = 0;
        float d8[8]; int i8[8];
        #pragma unroll
        for (int k = 0; k < 8; ++k) {
            float v0 = sd[pp][0][p0], v1 = sd[pp][1][p1];
            float v2 = sd[pp][2][p2], v3 = sd[pp][3][p3];
            float m01 = v0; int q01 = 0; if (v1 < m01) { m01 = v1; q01 = 1; }
            float m23 = v2; int q23 = 2; if (v3 < m23) { m23 = v3; q23 = 3; }
            float mv = m01; int qq = q01; if (m23 < m01) { mv = m23; qq = q23; }
            d8[k] = mv;
            if      (qq == 0) i8[k] = si[pp][0][p0++];
            else if (qq == 1) i8[k] = si[pp][1][p1++];
            else if (qq == 2) i8[k] = si[pp][2][p2++];
            else              i8[k] = si[pp][3][p3++];
        }
        float w[8], s = 0.f;
        #pragma unroll
        for (int j = 0; j < 8; ++j) { w[j] = 1.f / (d8[j] + 1e-8f); s += w[j]; }
        float inv = 1.f / (s + 1e-8f);
        const int nn = blockIdx.x * 64 + pp;
        size_t base = ((size_t)b * Npts + nn) * 8;
        #pragma unroll
        for (int j = 0; j < 8; ++j) { out_i[base + j] = i8[j]; out_w[base + j] = w[j] * inv; }
    }
}

// ---------------------------------------------------------------------------
// convert fp32 -> fp16
// ---------------------------------------------------------------------------
__global__ __launch_bounds__(256)
void cvt_x_half(const float* __restrict__ x, __half* __restrict__ hi, int n4)
{
    int i = blockIdx.x * 256 + threadIdx.x;
    if (i >= n4) return;
    float4 v = ((const float4*)x)[i];
    ((__half2*)hi)[i*2+0] = __halves2half2(__float2half_rn(v.x), __float2half_rn(v.y));
    ((__half2*)hi)[i*2+1] = __halves2half2(__float2half_rn(v.z), __float2half_rn(v.w));
}

// ---------------------------------------------------------------------------
// combine: v = ReLU(sc*(H[n] + sum_j w_j G[idx_j]) + bb) -> single fp16 plane
// ---------------------------------------------------------------------------
__global__ __launch_bounds__(256)
void combine_bn_relu(const float* __restrict__ H,    // [B][Np][640]
                     const float* __restrict__ G,    // [B][Ng][640]
                     const int*   __restrict__ knn_i,
                     const float* __restrict__ knn_w,
                     const float* __restrict__ bias,
                     const float* __restrict__ gamma,
                     const float* __restrict__ beta,
                     __half* __restrict__ Yh, int Np, int Ng)
{
    __shared__ float s_sc[640], s_bb[640];
    const float BNS = 0.99999500003749968f;   // 1/sqrt(1+1e-5)
    for (int c = threadIdx.x; c < 640; c += 256) {
        float sc = __ldg(gamma + c) * BNS;
        s_sc[c] = sc;
        s_bb[c] = sc * __ldg(bias + c) + __ldg(beta + c);
    }
    __syncthreads();
    const int b    = blockIdx.y;
    const int warp = threadIdx.x >> 5, lane = threadIdx.x & 31;
    const int n    = blockIdx.x * 8 + warp;
    const size_t pbase = (size_t)b * Np + n;

    int idx[8]; float w8[8];
    const int*   ip = knn_i + pbase * 8;
    const float* wp = knn_w + pbase * 8;
    #pragma unroll
    for (int j = 0; j < 8; ++j) { idx[j] = __ldg(ip + j); w8[j] = __ldg(wp + j); }

    const float* h = H + pbase * 640;
    float acc[20];
    #pragma unroll
    for (int r = 0; r < 20; ++r) acc[r] = __ldg(h + lane + 32 * r);
    #pragma unroll
    for (int j = 0; j < 8; ++j) {
        const float* g = G + ((size_t)b * Ng + idx[j]) * 640;
        const float wj = w8[j];
        #pragma unroll
        for (int r = 0; r < 20; ++r) acc[r] += wj * __ldg(g + lane + 32 * r);
    }
    #pragma unroll
    for (int r = 0; r < 20; ++r) {
        int c = lane + 32 * r;
        float v = fmaxf(s_sc[c] * acc[r] + s_bb[c], 0.f);
        Yh[pbase * 640 + c] = __float2half_rn(v);
    }
}

// ---------------------------------------------------------------------------
// mma.sync fp16 GEMM:  D[o][n] = sum_k W[o][k] * X[n][k]
// Single fp16 plane each for W and X, fp32 accum.
// Block 128x128, K-chunk 64, 512 threads = 4x4 warps, warp tile 32x32.
// 3-stage cp.async pipeline (2 planes/stage), one __syncthreads per chunk.
// Smem row stride 144 B (72 halves): LDSM conflict-free (144 mod 128 = 16).
// mode: 0 = channel-major fp32 + BN+ReLU
//       1 = point-major fp16 + BN+ReLU
//       2 = point-major fp32 raw
// ---------------------------------------------------------------------------
#define PLANE_BYTES 18432              // 128 rows x 144 B
#define STAGE_BYTES (2 * PLANE_BYTES)  // W, X
#define GEMM_SMEM   (3 * STAGE_BYTES)  // 110592; epilogue (67584 B) reuses it

__global__ __launch_bounds__(512)
void gemm_mma(const __half* __restrict__ Wh, int ldW,
              const __half* __restrict__ Xh,
              float* __restrict__ Yf, __half* __restrict__ Yhp,
              const float* __restrict__ bias, const float* __restrict__ gamma,
              const float* __restrict__ beta,
              int K, int N, int O, int mode)
{
    extern __shared__ char dsm[];
    const uint32_t sbase = smem_u32_of(dsm);
    const int t = threadIdx.x, lane = t & 31, w = t >> 5;
    const int wm = w >> 2, wn = w & 3;
    const int b  = blockIdx.z;
    const int n0 = blockIdx.x * 128;
    const int o0 = blockIdx.y * 128;

    const __half* srcs[2];
    srcs[0] = Wh + (size_t)o0 * ldW;
    srcs[1] = Xh + ((size_t)b * N + n0) * K;
    int lds[2] = { ldW, K };

    float accm[2][4][4];
    #pragma unroll
    for (int i = 0; i < 2; ++i)
        #pragma unroll
        for (int j = 0; j < 4; ++j)
            #pragma unroll
            for (int e = 0; e < 4; ++e) accm[i][j][e] = 0.f;

    // stage loader: 2 planes x 128 rows x 64 halves, padded stride 72 halves.
    // 128 rows x 8 x 16B chunks = 1024 cp16 per plane = TWO per thread per plane.
    auto cp_stage = [&](int k0, int buf) {
        uint32_t sb = sbase + buf * STAGE_BYTES;
        #pragma unroll
        for (int pl = 0; pl < 2; ++pl) {
            #pragma unroll
            for (int u = 0; u < 2; ++u) {
                int idx = t * 2 + u;            // 0..1023
                int row = idx >> 3, c8 = idx & 7;
                cp16(sb + pl * PLANE_BYTES + row * 144 + c8 * 16,
                     srcs[pl] + (size_t)row * lds[pl] + k0 + c8 * 8);
            }
        }
        asm volatile("cp.async.commit_group;" ::: "memory");
    };

    const int g = lane >> 3;
    const int arow_off = (g & 1) * 8 + (lane & 7);
    const int acol_off = (g >> 1) * 8;
    const int brow_off = (g >> 1) * 8 + (lane & 7);
    const int bcol_off = (g & 1) * 8;

    const int nc = K >> 6;
    cp_stage(0, 0);
    if (nc > 1) cp_stage(64, 1);

    int buf = 0;
    for (int it = 0; it < nc; ++it) {
        if (it + 1 < nc) asm volatile("cp.async.wait_group 1;" ::: "memory");
        else             asm volatile("cp.async.wait_group 0;" ::: "memory");
        __syncthreads();
        if (it + 2 < nc) {
            int nb = buf + 2; if (nb >= 3) nb -= 3;
            cp_stage((it + 2) << 6, nb);
        }

        const uint32_t pA = sbase + buf * STAGE_BYTES;
        const uint32_t pB = pA + PLANE_BYTES;
        #pragma unroll
        for (int ks = 0; ks < 4; ++ks) {
            uint32_t ah[2][4];
            #pragma unroll
            for (int mt = 0; mt < 2; ++mt) {
                uint32_t ad = (uint32_t)(wm * 32 + mt * 16 + arow_off) * 144
                            + (uint32_t)(ks * 16 + acol_off) * 2;
                ldsm4(ah[mt], pA + ad);
            }
            #pragma unroll
            for (int np = 0; np < 2; ++np) {
                uint32_t bd = (uint32_t)(wn * 32 + np * 16 + brow_off) * 144
                            + (uint32_t)(ks * 16 + bcol_off) * 2;
                uint32_t bh[4];
                ldsm4(bh, pB + bd);
                #pragma unroll
                for (int mt = 0; mt < 2; ++mt)
                    #pragma unroll
                    for (int nj = 0; nj < 2; ++nj)
                        mma16816(accm[mt][np * 2 + nj], ah[mt], bh + nj * 2);
            }
        }
        ++buf; if (buf == 3) buf = 0;
    }
    __syncthreads();   // all MMA reads done before smem reuse

    // ---- epilogue through smem (stride 132 floats) ----
    float* smf = (float*)dsm;
    const int base_r = wm * 32 + (lane >> 2);
    const int base_c = wn * 32 + (lane & 3) * 2;
    #pragma unroll
    for (int mt = 0; mt < 2; ++mt)
        #pragma unroll
        for (int nt = 0; nt < 4; ++nt) {
            float v0 = accm[mt][nt][0];
            float v1 = accm[mt][nt][1];
            float v2 = accm[mt][nt][2];
            float v3 = accm[mt][nt][3];
            int r = base_r + mt * 16, c = base_c + (nt >> 1) * 16 + (nt & 1) * 8;
            if (mode == 0) {
                smf[r * 132 + c]           = v0;
                smf[r * 132 + c + 1]       = v1;
                smf[(r + 8) * 132 + c]     = v2;
                smf[(r + 8) * 132 + c + 1] = v3;
            } else {
                smf[c * 132 + r]           = v0;
                smf[(c + 1) * 132 + r]     = v1;
                smf[c * 132 + r + 8]       = v2;
                smf[(c + 1) * 132 + r + 8] = v3;
            }
        }
    __syncthreads();

    const float BNS = 0.99999500003749968f;
    if (mode == 0) {
        int o = t >> 2, nch = (t & 3) * 32;
        float sc = __ldg(gamma + o0 + o) * BNS;
        float bb = sc * __ldg(bias + o0 + o) + __ldg(beta + o0 + o);
        float* dst = Yf + ((size_t)b * O + o0 + o) * N + n0 + nch;
        #pragma unroll
        for (int j = 0; j < 32; j += 4) {
            float4 v;
            v.x = fmaxf(sc * smf[o * 132 + nch + j]     + bb, 0.f);
            v.y = fmaxf(sc * smf[o * 132 + nch + j + 1] + bb, 0.f);
            v.z = fmaxf(sc * smf[o * 132 + nch + j + 2] + bb, 0.f);
            v.w = fmaxf(sc * smf[o * 132 + nch + j + 3] + bb, 0.f);
            *(float4*)(dst + j) = v;
        }
    } else if (mode == 2) {
        int n = t >> 2, och = (t & 3) * 32;
        float* dst = Yf + ((size_t)b * N + n0 + n) * O + o0 + och;
        #pragma unroll
        for (int j = 0; j < 32; j += 4) {
            float4 v;
            v.x = smf[n * 132 + och + j];
            v.y = smf[n * 132 + och + j + 1];
            v.z = smf[n * 132 + och + j + 2];
            v.w = smf[n * 132 + och + j + 3];
            *(float4*)(dst + j) = v;
        }
    } else {
        int n = t >> 2, och = (t & 3) * 32;
        size_t off = ((size_t)b * N + n0 + n) * O + o0 + och;
        #pragma unroll
        for (int j0 = 0; j0 < 32; j0 += 8) {
            union { __half h[8]; uint4 u; } Hh;
            #pragma unroll
            for (int j = 0; j < 8; ++j) {
                int o = o0 + och + j0 + j;
                float sc = __ldg(gamma + o) * BNS;
                float bb = sc * __ldg(bias + o) + __ldg(beta + o);
                float v = fmaxf(sc * smf[n * 132 + och + j0 + j] + bb, 0.f);
                Hh.h[j] = __float2half_rn(v);
            }
            *(uint4*)(Yhp + off + j0) = Hh.u;
        }
    }
}

// ---------------------------------------------------------------------------
extern "C" void kernel_launch(void* const* d_in, const int* in_sizes, int n_in,
                              void* d_out, int out_size)
{
    const float* radar = (const float*)d_in[0];
    const float* l1f   = (const float*)d_in[1];
    const float* l2f   = (const float*)d_in[2];
    const float* l0_l1 = (const float*)d_in[3];
    const float* l1_l2 = (const float*)d_in[4];
    const float* w21a  = (const float*)d_in[5];
    const float* b21a  = (const float*)d_in[6];
    const float* g21a  = (const float*)d_in[7];
    const float* be21a = (const float*)d_in[8];
    const float* w21b  = (const float*)d_in[9];
    const float* b21b  = (const float*)d_in[10];
    const float* g21b  = (const float*)d_in[11];
    const float* be21b = (const float*)d_in[12];
    const float* w10a  = (const float*)d_in[13];
    const float* b10a  = (const float*)d_in[14];
    const float* g10a  = (const float*)d_in[15];
    const float* be10a = (const float*)d_in[16];
    const float* w10b  = (const float*)d_in[17];
    const float* b10b  = (const float*)d_in[18];
    const float* g10b  = (const float*)d_in[19];
    const float* be10b = (const float*)d_in[20];

    cudaFuncSetAttribute(gemm_mma, cudaFuncAttributeMaxDynamicSharedMemorySize, GEMM_SMEM);

    __half *l1h,*l2h,*rdh;
    __half *w21ah,*w21bh,*w10ah,*w10bh;
    __half *Y1h,*Fh,*Y3h;
    float *G2,*H1,*G,*Hr,*w1,*w0;
    int *i1,*i0;
    cudaGetSymbolAddress((void**)&l1h, g_l1h);
    cudaGetSymbolAddress((void**)&l2h, g_l2h);
    cudaGetSymbolAddress((void**)&rdh, g_rdh);
    cudaGetSymbolAddress((void**)&w21ah, g_w21ah);
    cudaGetSymbolAddress((void**)&w21bh, g_w21bh);
    cudaGetSymbolAddress((void**)&w10ah, g_w10ah);
    cudaGetSymbolAddress((void**)&w10bh, g_w10bh);
    cudaGetSymbolAddress((void**)&Y1h, g_Y1h);
    cudaGetSymbolAddress((void**)&Fh,  g_Fh);
    cudaGetSymbolAddress((void**)&Y3h, g_Y3h);
    cudaGetSymbolAddress((void**)&G2, g_G2);     cudaGetSymbolAddress((void**)&H1, g_H1);
    cudaGetSymbolAddress((void**)&G,  g_G);      cudaGetSymbolAddress((void**)&Hr, g_Hr);
    cudaGetSymbolAddress((void**)&i1, g_i1);     cudaGetSymbolAddress((void**)&w1, g_w1);
    cudaGetSymbolAddress((void**)&i0, g_i0);     cudaGetSymbolAddress((void**)&w0, g_w0);

    // knn + converts
    knn_topk<<<dim3(N1_/64, B_), 256>>>(l1_l2, N2_, N1_, i1, w1);
    knn_topk<<<dim3(N0_/64, B_), 256>>>(l0_l1, N1_, N0_, i0, w0);
    cvt_x_half<<<(B_*N1_*128/4 + 255)/256, 256>>>(l1f, l1h, B_*N1_*128/4);
    cvt_x_half<<<(B_*N2_*192/4 + 255)/256, 256>>>(l2f, l2h, B_*N2_*192/4);
    cvt_x_half<<<(640*320/4 + 255)/256, 256>>>(w21a, w21ah, 640*320/4);

    // H1 = W21a[:,0:128]*l1f ; G2 = W21a[:,128:320]*l2f
    gemm_mma<<<dim3(N1_/128, 5, B_), 512, GEMM_SMEM>>>(w21ah, 320, l1h,
        H1, nullptr, nullptr, nullptr, nullptr, 128, N1_, 640, 2);
    gemm_mma<<<dim3(N2_/128, 5, B_), 512, GEMM_SMEM>>>(w21ah+128, 320, l2h,
        G2, nullptr, nullptr, nullptr, nullptr, 192, N2_, 640, 2);
    combine_bn_relu<<<dim3(N1_/8, B_), 256>>>(H1, G2, i1, w1, b21a, g21a, be21a, Y1h, N1_, N2_);

    cvt_x_half<<<(640*640/4 + 255)/256, 256>>>(w21b, w21bh, 640*640/4);
    gemm_mma<<<dim3(N1_/128, 5, B_), 512, GEMM_SMEM>>>(w21bh, 640, Y1h,
        nullptr, Fh, b21b, g21b, be21b, 640, N1_, 640, 1);

    cvt_x_half<<<(640*704/4 + 255)/256, 256>>>(w10a, w10ah, 640*704/4);
    cvt_x_half<<<(B_*N0_*64/4 + 255)/256, 256>>>(radar, rdh, B_*N0_*64/4);
    gemm_mma<<<dim3(N1_/128, 5, B_), 512, GEMM_SMEM>>>(w10ah+64, 704, Fh,
        G, nullptr, nullptr, nullptr, nullptr, 640, N1_, 640, 2);
    gemm_mma<<<dim3(N0_/128, 5, B_), 512, GEMM_SMEM>>>(w10ah, 704, rdh,
        Hr, nullptr, nullptr, nullptr, nullptr, 64, N0_, 640, 2);
    combine_bn_relu<<<dim3(N0_/8, B_), 256>>>(Hr, G, i0, w0, b10a, g10a, be10a, Y3h, N0_, N1_);

    cvt_x_half<<<(768*640/4 + 255)/256, 256>>>(w10b, w10bh, 768*640/4);
    gemm_mma<<<dim3(N0_/128, 6, B_), 512, GEMM_SMEM>>>(w10bh, 640, Y3h,
        (float*)d_out, nullptr, b10b, g10b, be10b, 640, N0_, 768, 0);
}